// round 5
// baseline (speedup 1.0000x reference)
#include <cuda_runtime.h>
#include <cstdint>
#include <cstddef>

// ---------------- problem constants ----------------
#define B_   2
#define L_   2048
#define DM   2048          // d_model
#define DI   4096          // d_inner
#define EI   8192          // 2*d_inner
#define DS   16            // d_state
#define DTR  128           // dt_rank
#define XD   160           // dt_rank + 2*d_state
#define ML   (B_*L_)       // 4096 rows

// ---------------- scratch (device globals; no allocation allowed) ----------------
__device__ float g_xz  [(size_t)ML * EI];   // in_proj output [b*l, 8192]
__device__ float g_xc  [(size_t)ML * DI];   // conv+silu x    [b*l, 4096]
__device__ float g_xdbl[(size_t)ML * XD];   // x_proj output  [b*l, 160]
__device__ float g_dt  [(size_t)ML * DI];   // softplus(dt)   [b*l, 4096]
__device__ float g_y   [(size_t)ML * DI];   // scan output (tf32-rounded) [b*l, 4096]
// tf32-pre-rounded operand copies
__device__ float g_hsc [(size_t)ML * DM];   // rounded hidden_states
__device__ float g_winc[(size_t)EI * DM];   // rounded in_proj_weight
__device__ float g_dtwc[(size_t)DI * DTR];  // rounded dt_proj_weight
__device__ float g_outwc[(size_t)DM * DI];  // rounded out_proj_weight
__device__ float g_dtlo[(size_t)ML * DTR];  // rounded dt_lo (compact, lda=128)

__device__ __forceinline__ unsigned f2tf32(float f) {
    unsigned u;
    asm("cvt.rna.tf32.f32 %0, %1;" : "=r"(u) : "f"(f));
    return u;
}
__device__ __forceinline__ float tf32r(float f) {
    return __uint_as_float(f2tf32(f));
}

// ---------------- elementwise tf32 rounding pass (float4) ----------------
__global__ __launch_bounds__(256)
void round_tf32_kernel(const float* __restrict__ in, float* __restrict__ out, size_t n4)
{
    size_t i = (size_t)blockIdx.x * blockDim.x + threadIdx.x;
    if (i < n4) {
        float4 v = ((const float4*)in)[i];
        v.x = tf32r(v.x); v.y = tf32r(v.y); v.z = tf32r(v.z); v.w = tf32r(v.w);
        ((float4*)out)[i] = v;
    }
}

// ================= TF32 tensor-core GEMM, cp.async 3-stage =================
// C[M,N] = A[M,K] * B[N,K]^T. BM=BN=128, BK=16, 256 thr, 8 warps 2(m)x4(n),
// warp tile 64x32. Inputs are PRE-ROUNDED to tf32; loop is pure LDS+HMMA.
// EPI: 0 = none, 1 = softplus(v + bias[n])

__device__ __forceinline__ void cp16(float* smem_dst, const float* gmem_src) {
    unsigned s = (unsigned)__cvta_generic_to_shared(smem_dst);
    asm volatile("cp.async.cg.shared.global [%0], [%1], 16;\n" :: "r"(s), "l"(gmem_src));
}
__device__ __forceinline__ void cp_commit() {
    asm volatile("cp.async.commit_group;\n");
}
__device__ __forceinline__ void cp_wait1() {
    asm volatile("cp.async.wait_group 1;\n");
}

#define TSZ 2048   // floats per stage per matrix (128 rows * 16)

template<int EPI>
__global__ __launch_bounds__(256)
void mma_gemm(int M, int N, int K,
              const float* __restrict__ A, int lda,
              const float* __restrict__ Bw, int ldb,
              float* __restrict__ C, int ldc,
              const float* __restrict__ bias)
{
    extern __shared__ float smem[];
    float* As = smem;            // 3 stages * 2048
    float* Bs = smem + 3*TSZ;    // 3 stages * 2048

    const int tid  = threadIdx.x;
    const int lane = tid & 31;
    const int warp = tid >> 5;
    const int wm   = (warp & 1) * 64;
    const int wn   = (warp >> 1) * 32;
    const int bm   = blockIdx.y * 128;
    const int bn   = blockIdx.x * 128;

    // ---- loader indices (cp.async, 16B per op, 4 ops/thread) ----
    const int lr  = tid >> 2;                      // row 0..63 (and +64)
    const int q   = tid & 3;                       // k-quad
    const int swl = (lr ^ (lr >> 2)) & 3;          // row swizzle
    const int dA0 = lr*16 + ((q ^ swl) << 2);
    const int dA1 = dA0 + 64*16;

    const float* gA0 = A  + (size_t)(bm + lr)      * lda + q*4;
    const float* gA1 = A  + (size_t)(bm + lr + 64) * lda + q*4;
    const float* gB0 = Bw + (size_t)(bn + lr)      * ldb + q*4;
    const float* gB1 = Bw + (size_t)(bn + lr + 64) * ldb + q*4;

    // ---- fragment indices ----
    const int u    = lane >> 2;                    // 0..7
    const int li   = lane & 3;
    const int su   = (u ^ (u >> 2)) & 3;
    const int a_row = wm + u;
    const int b_row = wn + u;

    float acc[4][4][4];
    #pragma unroll
    for (int i = 0; i < 4; i++)
        #pragma unroll
        for (int j = 0; j < 4; j++)
            #pragma unroll
            for (int r = 0; r < 4; r++) acc[i][j][r] = 0.0f;

    const int KT = K / 16;

    // ---- prologue: stage 0 and 1 ----
    {
        cp16(As + dA0, gA0); cp16(As + dA1, gA1);
        cp16(Bs + dA0, gB0); cp16(Bs + dA1, gB1);
        cp_commit();
        cp16(As + TSZ + dA0, gA0 + 16); cp16(As + TSZ + dA1, gA1 + 16);
        cp16(Bs + TSZ + dA0, gB0 + 16); cp16(Bs + TSZ + dA1, gB1 + 16);
        cp_commit();
    }
    cp_wait1();
    __syncthreads();

    for (int kt = 0; kt < KT; kt++) {
        const int cur = kt % 3;
        if (kt + 2 < KT) {
            const int st = (kt + 2) % 3;
            const size_t ko = (size_t)(kt + 2) * 16;
            cp16(As + st*TSZ + dA0, gA0 + ko); cp16(As + st*TSZ + dA1, gA1 + ko);
            cp16(Bs + st*TSZ + dA0, gB0 + ko); cp16(Bs + st*TSZ + dA1, gB1 + ko);
        }
        cp_commit();

        const float* asb = As + cur*TSZ;
        const float* bsb = Bs + cur*TSZ;
        #pragma unroll
        for (int ks = 0; ks < 2; ks++) {
            const int c0  = (((2*ks + 0) ^ su    ) << 2) + li;
            const int c1  = (((2*ks + 1) ^ su    ) << 2) + li;
            const int c0h = (((2*ks + 0) ^ su ^ 2) << 2) + li;
            const int c1h = (((2*ks + 1) ^ su ^ 2) << 2) + li;

            unsigned af[4][4];
            unsigned bf[4][2];
            #pragma unroll
            for (int i = 0; i < 4; i++) {
                const int r = (a_row + i*16) * 16;
                af[i][0] = __float_as_uint(asb[r        + c0 ]);
                af[i][1] = __float_as_uint(asb[r + 8*16 + c0h]);
                af[i][2] = __float_as_uint(asb[r        + c1 ]);
                af[i][3] = __float_as_uint(asb[r + 8*16 + c1h]);
            }
            #pragma unroll
            for (int j = 0; j < 4; j++) {
                const int r = (b_row + j*8) * 16;
                bf[j][0] = __float_as_uint(bsb[r + ((j & 1) ? c0h : c0)]);
                bf[j][1] = __float_as_uint(bsb[r + ((j & 1) ? c1h : c1)]);
            }
            #pragma unroll
            for (int i = 0; i < 4; i++)
                #pragma unroll
                for (int j = 0; j < 4; j++) {
                    asm volatile(
                        "mma.sync.aligned.m16n8k8.row.col.f32.tf32.tf32.f32 "
                        "{%0,%1,%2,%3}, {%4,%5,%6,%7}, {%8,%9}, {%0,%1,%2,%3};"
                        : "+f"(acc[i][j][0]), "+f"(acc[i][j][1]),
                          "+f"(acc[i][j][2]), "+f"(acc[i][j][3])
                        : "r"(af[i][0]), "r"(af[i][1]), "r"(af[i][2]), "r"(af[i][3]),
                          "r"(bf[j][0]), "r"(bf[j][1]));
                }
        }

        cp_wait1();
        __syncthreads();
    }

    // ---- epilogue ----
    #pragma unroll
    for (int i = 0; i < 4; i++) {
        const int r0 = bm + wm + i*16 + u;
        #pragma unroll
        for (int j = 0; j < 4; j++) {
            const int c0 = bn + wn + j*8 + li*2;
            float v0 = acc[i][j][0], v1 = acc[i][j][1];
            float v2 = acc[i][j][2], v3 = acc[i][j][3];
            if (EPI == 1) {
                const float bA = bias[c0], bB = bias[c0+1];
                v0 += bA; v1 += bB; v2 += bA; v3 += bB;
                v0 = (v0 > 20.0f) ? v0 : log1pf(__expf(v0));
                v1 = (v1 > 20.0f) ? v1 : log1pf(__expf(v1));
                v2 = (v2 > 20.0f) ? v2 : log1pf(__expf(v2));
                v3 = (v3 > 20.0f) ? v3 : log1pf(__expf(v3));
            }
            *(float2*)&C[(size_t)r0 * ldc + c0]     = make_float2(v0, v1);
            *(float2*)&C[(size_t)(r0+8) * ldc + c0] = make_float2(v2, v3);
        }
    }
}

// ---------------- fp32 tiled SGEMM (x_proj: N=160) ----------------
// Also writes tf32-rounded copy of cols [0,DTR) into C2 (compact lda=DTR).
template<int BM, int BN, int BK, int TM, int TN>
__global__ __launch_bounds__(256)
void sgemm_kernel(int M, int N, int K,
                  const float* __restrict__ A, int lda,
                  const float* __restrict__ Bw, int ldb,
                  float* __restrict__ C, int ldc,
                  float* __restrict__ C2)
{
    __shared__ float As[BK][BM];
    __shared__ float Bs[BK][BN];

    const int tid = threadIdx.x;
    const int tx  = tid & 15;
    const int ty  = tid >> 4;
    const int bm  = blockIdx.y * BM;
    const int bn  = blockIdx.x * BN;

    float acc[TM][TN];
    #pragma unroll
    for (int i = 0; i < TM; i++)
        #pragma unroll
        for (int j = 0; j < TN; j++) acc[i][j] = 0.0f;

    const int a_m = tid / (BK/4);
    const int a_k = (tid % (BK/4)) * 4;
    const int b_n = tid / (BK/4);
    const int b_k = (tid % (BK/4)) * 4;

    for (int k0 = 0; k0 < K; k0 += BK) {
        if (tid < (BM*BK/4)) {
            float4 v = *(const float4*)&A[(size_t)(bm + a_m)*lda + k0 + a_k];
            As[a_k+0][a_m] = v.x; As[a_k+1][a_m] = v.y;
            As[a_k+2][a_m] = v.z; As[a_k+3][a_m] = v.w;
        }
        if (tid < (BN*BK/4)) {
            float4 v = *(const float4*)&Bw[(size_t)(bn + b_n)*ldb + k0 + b_k];
            Bs[b_k+0][b_n] = v.x; Bs[b_k+1][b_n] = v.y;
            Bs[b_k+2][b_n] = v.z; Bs[b_k+3][b_n] = v.w;
        }
        __syncthreads();

        #pragma unroll
        for (int k = 0; k < BK; k++) {
            float rm[TM], rn[TN];
            #pragma unroll
            for (int i = 0; i < TM; i++) rm[i] = As[k][ty*TM + i];
            #pragma unroll
            for (int j = 0; j < TN; j++) rn[j] = Bs[k][tx*TN + j];
            #pragma unroll
            for (int i = 0; i < TM; i++)
                #pragma unroll
                for (int j = 0; j < TN; j++)
                    acc[i][j] += rm[i] * rn[j];
        }
        __syncthreads();
    }

    #pragma unroll
    for (int i = 0; i < TM; i++) {
        const int m = bm + ty*TM + i;
        #pragma unroll
        for (int j = 0; j < TN; j++) {
            const int n = bn + tx*TN + j;
            C[(size_t)m*ldc + n] = acc[i][j];
            if (C2 && n < DTR)
                C2[(size_t)m*DTR + n] = tf32r(acc[i][j]);
        }
    }
}

// ---------------- depthwise causal conv(k=4) + bias + silu ----------------
__global__ __launch_bounds__(256)
void conv_silu_kernel(const float* __restrict__ xz,
                      const float* __restrict__ w,
                      const float* __restrict__ bias,
                      float* __restrict__ xc)
{
    const int d = blockIdx.x * blockDim.x + threadIdx.x;
    const int b = blockIdx.y;
    const float w0 = w[d*4+0], w1 = w[d*4+1], w2 = w[d*4+2], w3 = w[d*4+3];
    const float bi = bias[d];
    const float* px = xz + (size_t)b * L_ * EI + d;
    float*       po = xc + (size_t)b * L_ * DI + d;

    float x0 = 0.f, x1 = 0.f, x2 = 0.f;
    #pragma unroll 4
    for (int l = 0; l < L_; l++) {
        float x3 = px[(size_t)l * EI];
        float v  = w0*x0 + w1*x1 + w2*x2 + w3*x3 + bi;
        v = v / (1.0f + __expf(-v));
        po[(size_t)l * DI] = v;
        x0 = x1; x1 = x2; x2 = x3;
    }
}

// ---------------- selective scan (sequential over L) ----------------
// Writes y PRE-ROUNDED to tf32 (consumed only by out_proj).
__global__ __launch_bounds__(128)
void scan_kernel(const float* __restrict__ xz,
                 const float* __restrict__ xc,
                 const float* __restrict__ dt,
                 const float* __restrict__ xdbl,
                 const float* __restrict__ A_log,
                 const float* __restrict__ Dp,
                 float* __restrict__ y)
{
    const int b = blockIdx.y;
    const int d = blockIdx.x * blockDim.x + threadIdx.x;
    __shared__ float sBC[2][32];

    float negA[DS];
    #pragma unroll
    for (int n = 0; n < DS; n++) negA[n] = -__expf(A_log[d*DS + n]);

    bool chain = (negA[0] != 0.0f);
    #pragma unroll
    for (int n = 1; n < DS; n++) {
        float r = negA[n] - (float)(n+1) * negA[0];
        if (fabsf(r) > 1e-4f * fabsf(negA[n])) chain = false;
    }

    const float Dd = Dp[d];
    float h[DS];
    #pragma unroll
    for (int n = 0; n < DS; n++) h[n] = 0.0f;

    const size_t rb = (size_t)b * L_;
    const float* pdt = dt   + rb * DI + d;
    const float* pxc = xc   + rb * DI + d;
    const float* pz  = xz   + rb * EI + DI + d;
    const float* pbc = xdbl + rb * XD + DTR;
    float*       py  = y    + rb * DI + d;

    if (threadIdx.x < 32) sBC[0][threadIdx.x] = pbc[threadIdx.x];
    float dt_c = pdt[0], x_c = pxc[0], z_c = pz[0];
    __syncthreads();

    float dt_n = 0.f, x_n = 0.f, z_n = 0.f;
    for (int l = 0; l < L_; l++) {
        const int cur = l & 1, nxt = cur ^ 1;
        if (l + 1 < L_) {
            if (threadIdx.x < 32)
                sBC[nxt][threadIdx.x] = pbc[(size_t)(l+1) * XD + threadIdx.x];
            dt_n = pdt[(size_t)(l+1) * DI];
            x_n  = pxc[(size_t)(l+1) * DI];
            z_n  = pz [(size_t)(l+1) * EI];
        }

        const float dtv = dt_c;
        float dA[DS];
        if (chain) {
            float base = __expf(dtv * negA[0]);
            dA[0] = base;
            dA[1] = base * base;
            #pragma unroll
            for (int n = 2; n < DS; n++)
                dA[n] = dA[(n-1) >> 1] * dA[n >> 1];
        } else {
            #pragma unroll
            for (int n = 0; n < DS; n++) dA[n] = __expf(dtv * negA[n]);
        }

        const float du = dtv * x_c;
        float yv = 0.0f;
        #pragma unroll
        for (int n = 0; n < DS; n++) {
            h[n] = h[n] * dA[n] + du * sBC[cur][n];
            yv  += h[n] * sBC[cur][16 + n];
        }
        yv += x_c * Dd;
        const float zs = z_c / (1.0f + __expf(-z_c));
        py[(size_t)l * DI] = tf32r(yv * zs);

        dt_c = dt_n; x_c = x_n; z_c = z_n;
        __syncthreads();
    }
}

// ---------------- launch ----------------
extern "C" void kernel_launch(void* const* d_in, const int* in_sizes, int n_in,
                              void* d_out, int out_size)
{
    const float* hs    = (const float*)d_in[0];
    const float* w_in  = (const float*)d_in[1];
    const float* convw = (const float*)d_in[2];
    const float* convb = (const float*)d_in[3];
    const float* xpw   = (const float*)d_in[4];
    const float* dtw   = (const float*)d_in[5];
    const float* dtb   = (const float*)d_in[6];
    const float* outw  = (const float*)d_in[7];
    const float* Alog  = (const float*)d_in[8];
    const float* Dp    = (const float*)d_in[9];
    float*       out   = (float*)d_out;

    float *xz, *xc, *xdbl, *dtb_, *yb;
    float *hsc, *winc, *dtwc, *outwc, *dtlo;
    cudaGetSymbolAddress((void**)&xz,    g_xz);
    cudaGetSymbolAddress((void**)&xc,    g_xc);
    cudaGetSymbolAddress((void**)&xdbl,  g_xdbl);
    cudaGetSymbolAddress((void**)&dtb_,  g_dt);
    cudaGetSymbolAddress((void**)&yb,    g_y);
    cudaGetSymbolAddress((void**)&hsc,   g_hsc);
    cudaGetSymbolAddress((void**)&winc,  g_winc);
    cudaGetSymbolAddress((void**)&dtwc,  g_dtwc);
    cudaGetSymbolAddress((void**)&outwc, g_outwc);
    cudaGetSymbolAddress((void**)&dtlo,  g_dtlo);

    const dim3 t256(256);
    const size_t gsmem = 6 * TSZ * sizeof(float);   // 49152

    // 0) pre-round GEMM operands to tf32 (elementwise)
    {
        size_t n;
        n = (size_t)ML*DM/4;   round_tf32_kernel<<<(unsigned)((n+255)/256), t256>>>(hs,   hsc,   n);
        n = (size_t)EI*DM/4;   round_tf32_kernel<<<(unsigned)((n+255)/256), t256>>>(w_in, winc,  n);
        n = (size_t)DI*DTR/4;  round_tf32_kernel<<<(unsigned)((n+255)/256), t256>>>(dtw,  dtwc,  n);
        n = (size_t)DM*DI/4;   round_tf32_kernel<<<(unsigned)((n+255)/256), t256>>>(outw, outwc, n);
    }

    // 1) in_proj: xz[ML,EI] = hsc * winc^T
    mma_gemm<0><<<dim3(EI/128, ML/128), t256, gsmem>>>(
        ML, EI, DM, hsc, DM, winc, DM, xz, EI, nullptr);

    // 2) depthwise conv + silu
    conv_silu_kernel<<<dim3(DI/256, B_), t256>>>(xz, convw, convb, xc);

    // 3) x_proj (fp32, N=160); also emits rounded dt_lo compact copy
    sgemm_kernel<64,32,16,4,2><<<dim3(XD/32, ML/64), t256>>>(
        ML, XD, DI, xc, DI, xpw, DI, xdbl, XD, dtlo);

    // 4) dt_proj + softplus: A = rounded dt_lo (lda=DTR), B = rounded dtw
    mma_gemm<1><<<dim3(DI/128, ML/128), t256, gsmem>>>(
        ML, DI, DTR, dtlo, DTR, dtwc, DTR, dtb_, DI, dtb);

    // 5) selective scan (writes tf32-rounded y)
    scan_kernel<<<dim3(DI/128, B_), dim3(128)>>>(
        xz, xc, dtb_, xdbl, Alog, Dp, yb);

    // 6) out_proj: out = y * outwc^T
    mma_gemm<0><<<dim3(DM/128, ML/128), t256, gsmem>>>(
        ML, DM, DI, yb, DI, outwc, DI, out, DM, nullptr);
}

// round 6
// speedup vs baseline: 1.0839x; 1.0839x over previous
#include <cuda_runtime.h>
#include <cstdint>
#include <cstddef>

// ---------------- problem constants ----------------
#define B_   2
#define L_   2048
#define DM   2048          // d_model
#define DI   4096          // d_inner
#define EI   8192          // 2*d_inner
#define DS   16            // d_state
#define DTR  128           // dt_rank
#define XD   160           // dt_rank + 2*d_state
#define ML   (B_*L_)       // 4096 rows

// ---------------- scratch (device globals; no allocation allowed) ----------------
__device__ float g_xz  [(size_t)ML * EI];
__device__ float g_xc  [(size_t)ML * DI];
__device__ float g_xdbl[(size_t)ML * XD];
__device__ float g_dt  [(size_t)ML * DI];
__device__ float g_y   [(size_t)ML * DI];   // scan output (tf32-rounded)
__device__ float g_hsc [(size_t)ML * DM];   // tf32-rounded hidden_states
__device__ float g_winc[(size_t)EI * DM];   // tf32-rounded in_proj_weight
__device__ float g_dtwc[(size_t)DI * DTR];  // tf32-rounded dt_proj_weight
__device__ float g_outwc[(size_t)DM * DI];  // tf32-rounded out_proj_weight
__device__ float g_dtlo[(size_t)ML * DTR];  // tf32-rounded dt_lo (compact)

__device__ __forceinline__ unsigned f2tf32(float f) {
    unsigned u;
    asm("cvt.rna.tf32.f32 %0, %1;" : "=r"(u) : "f"(f));
    return u;
}
__device__ __forceinline__ float tf32r(float f) {
    return __uint_as_float(f2tf32(f));
}

// ---------------- elementwise tf32 rounding pass (float4) ----------------
__global__ __launch_bounds__(256)
void round_tf32_kernel(const float* __restrict__ in, float* __restrict__ out, size_t n4)
{
    size_t i = (size_t)blockIdx.x * blockDim.x + threadIdx.x;
    if (i < n4) {
        float4 v = ((const float4*)in)[i];
        v.x = tf32r(v.x); v.y = tf32r(v.y); v.z = tf32r(v.z); v.w = tf32r(v.w);
        ((float4*)out)[i] = v;
    }
}

// ================= TF32 tensor-core GEMM: ldmatrix + cp.async, BK=32, 3-stage ====
// C[M,N] = A[M,K] * B[N,K]^T. BM=BN=128, 256 thr, 8 warps 2(m)x4(n), warp 64x32.
// Inputs pre-rounded to tf32. Smem rows = 32 floats (8 quads), quad swizzle q^(r&7).
// EPI: 0 = none, 1 = softplus(v + bias[n])

__device__ __forceinline__ void cp16(float* smem_dst, const float* gmem_src) {
    unsigned s = (unsigned)__cvta_generic_to_shared(smem_dst);
    asm volatile("cp.async.cg.shared.global [%0], [%1], 16;\n" :: "r"(s), "l"(gmem_src));
}
__device__ __forceinline__ void cp_commit() {
    asm volatile("cp.async.commit_group;\n");
}
__device__ __forceinline__ void cp_wait1() {
    asm volatile("cp.async.wait_group 1;\n");
}
__device__ __forceinline__ void ldsm4(unsigned& r0, unsigned& r1, unsigned& r2, unsigned& r3,
                                      unsigned addr) {
    asm volatile("ldmatrix.sync.aligned.m8n8.x4.shared.b16 {%0,%1,%2,%3}, [%4];"
                 : "=r"(r0), "=r"(r1), "=r"(r2), "=r"(r3) : "r"(addr));
}

#define TSZ32 4096          // floats per stage per matrix (128 rows * 32)
#define STB   16384u        // stage stride in bytes

template<int EPI>
__global__ __launch_bounds__(256, 2)
void mma_gemm(int M, int N, int K,
              const float* __restrict__ A, int lda,
              const float* __restrict__ Bw, int ldb,
              float* __restrict__ C, int ldc,
              const float* __restrict__ bias)
{
    extern __shared__ float smem[];
    float* As = smem;              // 3 stages * 4096 floats
    float* Bs = smem + 3*TSZ32;    // 3 stages * 4096 floats

    const int tid  = threadIdx.x;
    const int lane = tid & 31;
    const int warp = tid >> 5;
    const int wm   = (warp & 1) * 64;
    const int wn   = (warp >> 1) * 32;
    const int bm   = blockIdx.y * 128;
    const int bn   = blockIdx.x * 128;

    // ---- loader: thread t -> quad col q=t&7, rows r0, r0+32, r0+64, r0+96 ----
    const int q     = tid & 7;
    const int r0    = tid >> 3;
    const int pq    = q ^ (r0 & 7);           // physical quad (row-invariant: (r0+32i)&7 == r0&7)
    const int dBase = r0*32 + pq*4;           // float offset within stage; +i*1024 per row group

    const float* gA = A  + (size_t)(bm + r0) * lda + q*4;
    const float* gB = Bw + (size_t)(bn + r0) * ldb + q*4;

    // ---- ldmatrix per-lane addresses ----
    const int g    = lane >> 3;               // matrix slot 0..3
    const int kg   = g >> 1;                  // k-quad half within 8-wide k slice
    const int sub8 = (g & 1) << 3;            // row sub-block 0/8
    const int lr   = lane & 7;                // row within 8
    const unsigned aSh = (unsigned)__cvta_generic_to_shared(As);
    const unsigned bSh = (unsigned)__cvta_generic_to_shared(Bs);
    const unsigned aBase  = aSh + (unsigned)(wm + sub8 + lr) * 128;
    const unsigned bBase0 = bSh + (unsigned)(wn + sub8 + lr) * 128;
    const unsigned bBase1 = bBase0 + 16*128;
    unsigned tks[4];
    #pragma unroll
    for (int ks = 0; ks < 4; ks++)
        tks[ks] = (unsigned)(((((ks << 1) + kg) ^ lr) & 7) << 4);

    // ---- mma fragment/epilogue lane mapping ----
    const int u  = lane >> 2;
    const int li = lane & 3;

    float acc[4][4][4];
    #pragma unroll
    for (int i = 0; i < 4; i++)
        #pragma unroll
        for (int j = 0; j < 4; j++)
            #pragma unroll
            for (int r = 0; r < 4; r++) acc[i][j][r] = 0.0f;

    const int KT = K / 32;

    // ---- prologue: stages 0 and 1 ----
    #pragma unroll
    for (int s = 0; s < 2; s++) {
        const size_t ko = (size_t)s * 32;
        #pragma unroll
        for (int i = 0; i < 4; i++) {
            cp16(As + s*TSZ32 + dBase + i*1024, gA + (size_t)i*32*lda + ko);
            cp16(Bs + s*TSZ32 + dBase + i*1024, gB + (size_t)i*32*ldb + ko);
        }
        cp_commit();
    }
    cp_wait1();
    __syncthreads();

    for (int kt = 0; kt < KT; kt++) {
        const int cur = kt % 3;
        if (kt + 2 < KT) {
            const int st = (kt + 2) % 3;
            const size_t ko = (size_t)(kt + 2) * 32;
            #pragma unroll
            for (int i = 0; i < 4; i++) {
                cp16(As + st*TSZ32 + dBase + i*1024, gA + (size_t)i*32*lda + ko);
                cp16(Bs + st*TSZ32 + dBase + i*1024, gB + (size_t)i*32*ldb + ko);
            }
        }
        cp_commit();

        const unsigned aOff  = aBase  + (unsigned)cur * STB;
        const unsigned bOff0 = bBase0 + (unsigned)cur * STB;
        const unsigned bOff1 = bBase1 + (unsigned)cur * STB;

        #pragma unroll
        for (int ks = 0; ks < 4; ks++) {
            unsigned af[4][4];
            unsigned bf[4][2];
            #pragma unroll
            for (int i = 0; i < 4; i++)
                ldsm4(af[i][0], af[i][1], af[i][2], af[i][3],
                      aOff + (unsigned)i*2048 + tks[ks]);
            ldsm4(bf[0][0], bf[1][0], bf[0][1], bf[1][1], bOff0 + tks[ks]);
            ldsm4(bf[2][0], bf[3][0], bf[2][1], bf[3][1], bOff1 + tks[ks]);

            #pragma unroll
            for (int i = 0; i < 4; i++)
                #pragma unroll
                for (int j = 0; j < 4; j++) {
                    asm volatile(
                        "mma.sync.aligned.m16n8k8.row.col.f32.tf32.tf32.f32 "
                        "{%0,%1,%2,%3}, {%4,%5,%6,%7}, {%8,%9}, {%0,%1,%2,%3};"
                        : "+f"(acc[i][j][0]), "+f"(acc[i][j][1]),
                          "+f"(acc[i][j][2]), "+f"(acc[i][j][3])
                        : "r"(af[i][0]), "r"(af[i][1]), "r"(af[i][2]), "r"(af[i][3]),
                          "r"(bf[j][0]), "r"(bf[j][1]));
                }
        }

        cp_wait1();
        __syncthreads();
    }

    // ---- epilogue ----
    #pragma unroll
    for (int i = 0; i < 4; i++) {
        const int r0e = bm + wm + i*16 + u;
        #pragma unroll
        for (int j = 0; j < 4; j++) {
            const int c0 = bn + wn + j*8 + li*2;
            float v0 = acc[i][j][0], v1 = acc[i][j][1];
            float v2 = acc[i][j][2], v3 = acc[i][j][3];
            if (EPI == 1) {
                const float bA = bias[c0], bB = bias[c0+1];
                v0 += bA; v1 += bB; v2 += bA; v3 += bB;
                v0 = (v0 > 20.0f) ? v0 : log1pf(__expf(v0));
                v1 = (v1 > 20.0f) ? v1 : log1pf(__expf(v1));
                v2 = (v2 > 20.0f) ? v2 : log1pf(__expf(v2));
                v3 = (v3 > 20.0f) ? v3 : log1pf(__expf(v3));
            }
            *(float2*)&C[(size_t)r0e * ldc + c0]     = make_float2(v0, v1);
            *(float2*)&C[(size_t)(r0e+8) * ldc + c0] = make_float2(v2, v3);
        }
    }
}

// ---------------- fp32 tiled SGEMM (x_proj: N=160) ----------------
// Also writes tf32-rounded copy of cols [0,DTR) into C2 (compact lda=DTR).
template<int BM, int BN, int BK, int TM, int TN>
__global__ __launch_bounds__(256)
void sgemm_kernel(int M, int N, int K,
                  const float* __restrict__ A, int lda,
                  const float* __restrict__ Bw, int ldb,
                  float* __restrict__ C, int ldc,
                  float* __restrict__ C2)
{
    __shared__ float As[BK][BM];
    __shared__ float Bs[BK][BN];

    const int tid = threadIdx.x;
    const int tx  = tid & 15;
    const int ty  = tid >> 4;
    const int bm  = blockIdx.y * BM;
    const int bn  = blockIdx.x * BN;

    float acc[TM][TN];
    #pragma unroll
    for (int i = 0; i < TM; i++)
        #pragma unroll
        for (int j = 0; j < TN; j++) acc[i][j] = 0.0f;

    const int a_m = tid / (BK/4);
    const int a_k = (tid % (BK/4)) * 4;
    const int b_n = tid / (BK/4);
    const int b_k = (tid % (BK/4)) * 4;

    for (int k0 = 0; k0 < K; k0 += BK) {
        if (tid < (BM*BK/4)) {
            float4 v = *(const float4*)&A[(size_t)(bm + a_m)*lda + k0 + a_k];
            As[a_k+0][a_m] = v.x; As[a_k+1][a_m] = v.y;
            As[a_k+2][a_m] = v.z; As[a_k+3][a_m] = v.w;
        }
        if (tid < (BN*BK/4)) {
            float4 v = *(const float4*)&Bw[(size_t)(bn + b_n)*ldb + k0 + b_k];
            Bs[b_k+0][b_n] = v.x; Bs[b_k+1][b_n] = v.y;
            Bs[b_k+2][b_n] = v.z; Bs[b_k+3][b_n] = v.w;
        }
        __syncthreads();

        #pragma unroll
        for (int k = 0; k < BK; k++) {
            float rm[TM], rn[TN];
            #pragma unroll
            for (int i = 0; i < TM; i++) rm[i] = As[k][ty*TM + i];
            #pragma unroll
            for (int j = 0; j < TN; j++) rn[j] = Bs[k][tx*TN + j];
            #pragma unroll
            for (int i = 0; i < TM; i++)
                #pragma unroll
                for (int j = 0; j < TN; j++)
                    acc[i][j] += rm[i] * rn[j];
        }
        __syncthreads();
    }

    #pragma unroll
    for (int i = 0; i < TM; i++) {
        const int m = bm + ty*TM + i;
        #pragma unroll
        for (int j = 0; j < TN; j++) {
            const int n = bn + tx*TN + j;
            C[(size_t)m*ldc + n] = acc[i][j];
            if (C2 && n < DTR)
                C2[(size_t)m*DTR + n] = tf32r(acc[i][j]);
        }
    }
}

// ---------------- depthwise causal conv(k=4) + bias + silu ----------------
__global__ __launch_bounds__(256)
void conv_silu_kernel(const float* __restrict__ xz,
                      const float* __restrict__ w,
                      const float* __restrict__ bias,
                      float* __restrict__ xc)
{
    const int d = blockIdx.x * blockDim.x + threadIdx.x;
    const int b = blockIdx.y;
    const float w0 = w[d*4+0], w1 = w[d*4+1], w2 = w[d*4+2], w3 = w[d*4+3];
    const float bi = bias[d];
    const float* px = xz + (size_t)b * L_ * EI + d;
    float*       po = xc + (size_t)b * L_ * DI + d;

    float x0 = 0.f, x1 = 0.f, x2 = 0.f;
    #pragma unroll 4
    for (int l = 0; l < L_; l++) {
        float x3 = px[(size_t)l * EI];
        float v  = w0*x0 + w1*x1 + w2*x2 + w3*x3 + bi;
        v = v / (1.0f + __expf(-v));
        po[(size_t)l * DI] = v;
        x0 = x1; x1 = x2; x2 = x3;
    }
}

// ---------------- selective scan (sequential over L), prefetch distance 2 ----------------
__global__ __launch_bounds__(128)
void scan_kernel(const float* __restrict__ xz,
                 const float* __restrict__ xc,
                 const float* __restrict__ dt,
                 const float* __restrict__ xdbl,
                 const float* __restrict__ A_log,
                 const float* __restrict__ Dp,
                 float* __restrict__ y)
{
    const int b = blockIdx.y;
    const int d = blockIdx.x * blockDim.x + threadIdx.x;
    __shared__ float sBC[4][32];

    float negA[DS];
    #pragma unroll
    for (int n = 0; n < DS; n++) negA[n] = -__expf(A_log[d*DS + n]);

    bool chain = (negA[0] != 0.0f);
    #pragma unroll
    for (int n = 1; n < DS; n++) {
        float r = negA[n] - (float)(n+1) * negA[0];
        if (fabsf(r) > 1e-4f * fabsf(negA[n])) chain = false;
    }

    const float Dd = Dp[d];
    float h[DS];
    #pragma unroll
    for (int n = 0; n < DS; n++) h[n] = 0.0f;

    const size_t rb = (size_t)b * L_;
    const float* pdt = dt   + rb * DI + d;
    const float* pxc = xc   + rb * DI + d;
    const float* pz  = xz   + rb * EI + DI + d;
    const float* pbc = xdbl + rb * XD + DTR;
    float*       py  = y    + rb * DI + d;

    // preload l = 0, 1
    if (threadIdx.x < 32) {
        sBC[0][threadIdx.x] = pbc[threadIdx.x];
        sBC[1][threadIdx.x] = pbc[XD + threadIdx.x];
    }
    float dt0 = pdt[0],  x0v = pxc[0],  z0v = pz[0];
    float dt1 = pdt[DI], x1v = pxc[DI], z1v = pz[EI];
    __syncthreads();

    for (int l = 0; l < L_; l++) {
        float dt2 = 0.f, x2v = 0.f, z2v = 0.f;
        if (l + 2 < L_) {
            if (threadIdx.x < 32)
                sBC[(l+2)&3][threadIdx.x] = pbc[(size_t)(l+2) * XD + threadIdx.x];
            dt2 = pdt[(size_t)(l+2) * DI];
            x2v = pxc[(size_t)(l+2) * DI];
            z2v = pz [(size_t)(l+2) * EI];
        }

        const float* bc = sBC[l & 3];
        const float dtv = dt0;
        float dA[DS];
        if (chain) {
            float base = __expf(dtv * negA[0]);
            dA[0] = base;
            dA[1] = base * base;
            #pragma unroll
            for (int n = 2; n < DS; n++)
                dA[n] = dA[(n-1) >> 1] * dA[n >> 1];
        } else {
            #pragma unroll
            for (int n = 0; n < DS; n++) dA[n] = __expf(dtv * negA[n]);
        }

        const float du = dtv * x0v;
        float yv = 0.0f;
        #pragma unroll
        for (int n = 0; n < DS; n++) {
            h[n] = h[n] * dA[n] + du * bc[n];
            yv  += h[n] * bc[16 + n];
        }
        yv += x0v * Dd;
        const float zs = z0v / (1.0f + __expf(-z0v));
        py[(size_t)l * DI] = tf32r(yv * zs);

        dt0 = dt1; x0v = x1v; z0v = z1v;
        dt1 = dt2; x1v = x2v; z1v = z2v;
        __syncthreads();
    }
}

// ---------------- launch ----------------
extern "C" void kernel_launch(void* const* d_in, const int* in_sizes, int n_in,
                              void* d_out, int out_size)
{
    const float* hs    = (const float*)d_in[0];
    const float* w_in  = (const float*)d_in[1];
    const float* convw = (const float*)d_in[2];
    const float* convb = (const float*)d_in[3];
    const float* xpw   = (const float*)d_in[4];
    const float* dtw   = (const float*)d_in[5];
    const float* dtb   = (const float*)d_in[6];
    const float* outw  = (const float*)d_in[7];
    const float* Alog  = (const float*)d_in[8];
    const float* Dp    = (const float*)d_in[9];
    float*       out   = (float*)d_out;

    float *xz, *xc, *xdbl, *dtb_, *yb;
    float *hsc, *winc, *dtwc, *outwc, *dtlo;
    cudaGetSymbolAddress((void**)&xz,    g_xz);
    cudaGetSymbolAddress((void**)&xc,    g_xc);
    cudaGetSymbolAddress((void**)&xdbl,  g_xdbl);
    cudaGetSymbolAddress((void**)&dtb_,  g_dt);
    cudaGetSymbolAddress((void**)&yb,    g_y);
    cudaGetSymbolAddress((void**)&hsc,   g_hsc);
    cudaGetSymbolAddress((void**)&winc,  g_winc);
    cudaGetSymbolAddress((void**)&dtwc,  g_dtwc);
    cudaGetSymbolAddress((void**)&outwc, g_outwc);
    cudaGetSymbolAddress((void**)&dtlo,  g_dtlo);

    const dim3 t256(256);
    const size_t gsmem = 6 * TSZ32 * sizeof(float);   // 98304 bytes

    static int attr_set = 0;
    cudaFuncSetAttribute(mma_gemm<0>, cudaFuncAttributeMaxDynamicSharedMemorySize, (int)gsmem);
    cudaFuncSetAttribute(mma_gemm<1>, cudaFuncAttributeMaxDynamicSharedMemorySize, (int)gsmem);
    (void)attr_set;

    // 0) pre-round GEMM operands to tf32
    {
        size_t n;
        n = (size_t)ML*DM/4;   round_tf32_kernel<<<(unsigned)((n+255)/256), t256>>>(hs,   hsc,   n);
        n = (size_t)EI*DM/4;   round_tf32_kernel<<<(unsigned)((n+255)/256), t256>>>(w_in, winc,  n);
        n = (size_t)DI*DTR/4;  round_tf32_kernel<<<(unsigned)((n+255)/256), t256>>>(dtw,  dtwc,  n);
        n = (size_t)DM*DI/4;   round_tf32_kernel<<<(unsigned)((n+255)/256), t256>>>(outw, outwc, n);
    }

    // 1) in_proj: xz[ML,EI] = hsc * winc^T
    mma_gemm<0><<<dim3(EI/128, ML/128), t256, gsmem>>>(
        ML, EI, DM, hsc, DM, winc, DM, xz, EI, nullptr);

    // 2) depthwise conv + silu
    conv_silu_kernel<<<dim3(DI/256, B_), t256>>>(xz, convw, convb, xc);

    // 3) x_proj (fp32, N=160); emits rounded compact dt_lo
    sgemm_kernel<64,32,16,4,2><<<dim3(XD/32, ML/64), t256>>>(
        ML, XD, DI, xc, DI, xpw, DI, xdbl, XD, dtlo);

    // 4) dt_proj + softplus: A = rounded dt_lo (lda=DTR), B = rounded dtw
    mma_gemm<1><<<dim3(DI/128, ML/128), t256, gsmem>>>(
        ML, DI, DTR, dtlo, DTR, dtwc, DTR, dtb_, DI, dtb);

    // 5) selective scan (writes tf32-rounded y)
    scan_kernel<<<dim3(DI/128, B_), dim3(128)>>>(
        xz, xc, dtb_, xdbl, Alog, Dp, yb);

    // 6) out_proj: out = y * outwc^T
    mma_gemm<0><<<dim3(DM/128, ML/128), t256, gsmem>>>(
        ML, DM, DI, yb, DI, outwc, DI, out, DM, nullptr);
}

// round 8
// speedup vs baseline: 1.4817x; 1.3670x over previous
#include <cuda_runtime.h>
#include <cstdint>
#include <cstddef>

// ---------------- problem constants ----------------
#define B_   2
#define L_   2048
#define DM   2048          // d_model
#define DI   4096          // d_inner
#define EI   8192          // 2*d_inner
#define DS   16            // d_state
#define DTR  128           // dt_rank
#define XD   160           // dt_rank + 2*d_state
#define ML   (B_*L_)       // 4096 rows

// ---------------- scratch (device globals; no allocation allowed) ----------------
__device__ float g_xz  [(size_t)ML * EI];
__device__ float g_xc  [(size_t)ML * DI];
__device__ float g_xdbl[(size_t)ML * XD];
__device__ float g_dt  [(size_t)ML * DI];
__device__ float g_y   [(size_t)ML * DI];   // scan output (tf32-rounded)
__device__ float g_hsc [(size_t)ML * DM];   // tf32-rounded hidden_states
__device__ float g_winc[(size_t)EI * DM];   // tf32-rounded in_proj_weight
__device__ float g_dtwc[(size_t)DI * DTR];  // tf32-rounded dt_proj_weight
__device__ float g_outwc[(size_t)DM * DI];  // tf32-rounded out_proj_weight
__device__ float g_dtlo[(size_t)ML * DTR];  // tf32-rounded dt_lo (compact)

__device__ __forceinline__ unsigned f2tf32(float f) {
    unsigned u;
    asm("cvt.rna.tf32.f32 %0, %1;" : "=r"(u) : "f"(f));
    return u;
}
__device__ __forceinline__ float tf32r(float f) {
    return __uint_as_float(f2tf32(f));
}

// ---------------- elementwise tf32 rounding pass (float4) ----------------
__global__ __launch_bounds__(256)
void round_tf32_kernel(const float* __restrict__ in, float* __restrict__ out, size_t n4)
{
    size_t i = (size_t)blockIdx.x * blockDim.x + threadIdx.x;
    if (i < n4) {
        float4 v = ((const float4*)in)[i];
        v.x = tf32r(v.x); v.y = tf32r(v.y); v.z = tf32r(v.z); v.w = tf32r(v.w);
        ((float4*)out)[i] = v;
    }
}

// ---------------- async-copy + ldmatrix helpers ----------------
__device__ __forceinline__ void cp16(float* smem_dst, const float* gmem_src) {
    unsigned s = (unsigned)__cvta_generic_to_shared(smem_dst);
    asm volatile("cp.async.cg.shared.global [%0], [%1], 16;\n" :: "r"(s), "l"(gmem_src));
}
__device__ __forceinline__ void cp_commit() {
    asm volatile("cp.async.commit_group;\n");
}
__device__ __forceinline__ void cp_wait1() {
    asm volatile("cp.async.wait_group 1;\n");
}
__device__ __forceinline__ void ldsm4(unsigned& r0, unsigned& r1, unsigned& r2, unsigned& r3,
                                      unsigned addr) {
    asm volatile("ldmatrix.sync.aligned.m8n8.x4.shared.b16 {%0,%1,%2,%3}, [%4];"
                 : "=r"(r0), "=r"(r1), "=r"(r2), "=r"(r3) : "r"(addr));
}

// =========================================================================
// WIDE TF32 GEMM: BM=128, BN=256, BK=32, 512 threads (16 warps, 2m x 8n),
// warp tile 64x32, 3-stage cp.async, ldmatrix fragments. Inputs pre-rounded.
// =========================================================================
#define TSZ_A 4096          // floats per A stage (128*32)
#define TSZ_B 8192          // floats per B stage (256*32)
#define STB_A 16384u
#define STB_B 32768u

__global__ __launch_bounds__(512, 1)
void mma_gemm_wide(int M, int N, int K,
                   const float* __restrict__ A, int lda,
                   const float* __restrict__ Bw, int ldb,
                   float* __restrict__ C, int ldc)
{
    extern __shared__ float smem[];
    float* As = smem;               // 3 * 4096
    float* Bs = smem + 3*TSZ_A;     // 3 * 8192

    const int tid  = threadIdx.x;
    const int lane = tid & 31;
    const int warp = tid >> 5;              // 0..15
    const int wm   = (warp & 1) * 64;
    const int wn   = (warp >> 1) * 32;      // 0..224
    const int bm   = blockIdx.y * 128;
    const int bn   = blockIdx.x * 256;

    // ---- loaders: thread t -> row r0 = t>>3 (0..63), 16B chunk q = t&7 ----
    const int q     = tid & 7;
    const int r0    = tid >> 3;
    const int pq    = q ^ (r0 & 7);
    const int dBase = r0*32 + pq*4;         // +2048 floats per +64 rows

    const float* gA = A  + (size_t)(bm + r0) * lda + q*4;
    const float* gB = Bw + (size_t)(bn + r0) * ldb + q*4;

    // ---- ldmatrix lane addressing ----
    const int g    = lane >> 3;
    const int kg   = g >> 1;
    const int sub8 = (g & 1) << 3;
    const int lr   = lane & 7;
    const unsigned aSh = (unsigned)__cvta_generic_to_shared(As);
    const unsigned bSh = (unsigned)__cvta_generic_to_shared(Bs);
    const unsigned aBase  = aSh + (unsigned)(wm + sub8 + lr) * 128;
    const unsigned bBase0 = bSh + (unsigned)(wn + sub8 + lr) * 128;
    const unsigned bBase1 = bBase0 + 16*128;
    unsigned tks[4];
    #pragma unroll
    for (int ks = 0; ks < 4; ks++)
        tks[ks] = (unsigned)(((((ks << 1) + kg) ^ lr) & 7) << 4);

    const int u  = lane >> 2;
    const int li = lane & 3;

    float acc[4][4][4];
    #pragma unroll
    for (int i = 0; i < 4; i++)
        #pragma unroll
        for (int j = 0; j < 4; j++)
            #pragma unroll
            for (int r = 0; r < 4; r++) acc[i][j][r] = 0.0f;

    const int KT = K / 32;

    // ---- prologue: stages 0,1 ----
    #pragma unroll
    for (int s = 0; s < 2; s++) {
        const size_t ko = (size_t)s * 32;
        #pragma unroll
        for (int i = 0; i < 2; i++)
            cp16(As + s*TSZ_A + dBase + i*2048, gA + (size_t)i*64*lda + ko);
        #pragma unroll
        for (int i = 0; i < 4; i++)
            cp16(Bs + s*TSZ_B + dBase + i*2048, gB + (size_t)i*64*ldb + ko);
        cp_commit();
    }
    cp_wait1();
    __syncthreads();

    for (int kt = 0; kt < KT; kt++) {
        const int cur = kt % 3;
        if (kt + 2 < KT) {
            const int st = (kt + 2) % 3;
            const size_t ko = (size_t)(kt + 2) * 32;
            #pragma unroll
            for (int i = 0; i < 2; i++)
                cp16(As + st*TSZ_A + dBase + i*2048, gA + (size_t)i*64*lda + ko);
            #pragma unroll
            for (int i = 0; i < 4; i++)
                cp16(Bs + st*TSZ_B + dBase + i*2048, gB + (size_t)i*64*ldb + ko);
        }
        cp_commit();

        const unsigned aOff  = aBase  + (unsigned)cur * STB_A;
        const unsigned bOff0 = bBase0 + (unsigned)cur * STB_B;
        const unsigned bOff1 = bBase1 + (unsigned)cur * STB_B;

        #pragma unroll
        for (int ks = 0; ks < 4; ks++) {
            unsigned af[4][4];
            unsigned bf[4][2];
            #pragma unroll
            for (int i = 0; i < 4; i++)
                ldsm4(af[i][0], af[i][1], af[i][2], af[i][3],
                      aOff + (unsigned)i*2048 + tks[ks]);
            ldsm4(bf[0][0], bf[1][0], bf[0][1], bf[1][1], bOff0 + tks[ks]);
            ldsm4(bf[2][0], bf[3][0], bf[2][1], bf[3][1], bOff1 + tks[ks]);

            #pragma unroll
            for (int i = 0; i < 4; i++)
                #pragma unroll
                for (int j = 0; j < 4; j++) {
                    asm volatile(
                        "mma.sync.aligned.m16n8k8.row.col.f32.tf32.tf32.f32 "
                        "{%0,%1,%2,%3}, {%4,%5,%6,%7}, {%8,%9}, {%0,%1,%2,%3};"
                        : "+f"(acc[i][j][0]), "+f"(acc[i][j][1]),
                          "+f"(acc[i][j][2]), "+f"(acc[i][j][3])
                        : "r"(af[i][0]), "r"(af[i][1]), "r"(af[i][2]), "r"(af[i][3]),
                          "r"(bf[j][0]), "r"(bf[j][1]));
                }
        }

        cp_wait1();
        __syncthreads();
    }

    // ---- epilogue ----
    #pragma unroll
    for (int i = 0; i < 4; i++) {
        const int r0e = bm + wm + i*16 + u;
        #pragma unroll
        for (int j = 0; j < 4; j++) {
            const int c0 = bn + wn + j*8 + li*2;
            *(float2*)&C[(size_t)r0e * ldc + c0]     = make_float2(acc[i][j][0], acc[i][j][1]);
            *(float2*)&C[(size_t)(r0e+8) * ldc + c0] = make_float2(acc[i][j][2], acc[i][j][3]);
        }
    }
}

// ================= mma.sync TF32 GEMM BN=128 (dt_proj) =================
#define TSZ32 4096
#define STB   16384u

template<int EPI>
__global__ __launch_bounds__(256, 2)
void mma_gemm(int M, int N, int K,
              const float* __restrict__ A, int lda,
              const float* __restrict__ Bw, int ldb,
              float* __restrict__ C, int ldc,
              const float* __restrict__ bias)
{
    extern __shared__ float smem[];
    float* As = smem;
    float* Bs = smem + 3*TSZ32;

    const int tid  = threadIdx.x;
    const int lane = tid & 31;
    const int warp = tid >> 5;
    const int wm   = (warp & 1) * 64;
    const int wn   = (warp >> 1) * 32;
    const int bm   = blockIdx.y * 128;
    const int bn   = blockIdx.x * 128;

    const int q     = tid & 7;
    const int r0    = tid >> 3;
    const int pq    = q ^ (r0 & 7);
    const int dBase = r0*32 + pq*4;

    const float* gA = A  + (size_t)(bm + r0) * lda + q*4;
    const float* gB = Bw + (size_t)(bn + r0) * ldb + q*4;

    const int g    = lane >> 3;
    const int kg   = g >> 1;
    const int sub8 = (g & 1) << 3;
    const int lr   = lane & 7;
    const unsigned aSh = (unsigned)__cvta_generic_to_shared(As);
    const unsigned bSh = (unsigned)__cvta_generic_to_shared(Bs);
    const unsigned aBase  = aSh + (unsigned)(wm + sub8 + lr) * 128;
    const unsigned bBase0 = bSh + (unsigned)(wn + sub8 + lr) * 128;
    const unsigned bBase1 = bBase0 + 16*128;
    unsigned tks[4];
    #pragma unroll
    for (int ks = 0; ks < 4; ks++)
        tks[ks] = (unsigned)(((((ks << 1) + kg) ^ lr) & 7) << 4);

    const int u  = lane >> 2;
    const int li = lane & 3;

    float acc[4][4][4];
    #pragma unroll
    for (int i = 0; i < 4; i++)
        #pragma unroll
        for (int j = 0; j < 4; j++)
            #pragma unroll
            for (int r = 0; r < 4; r++) acc[i][j][r] = 0.0f;

    const int KT = K / 32;

    #pragma unroll
    for (int s = 0; s < 2; s++) {
        const size_t ko = (size_t)s * 32;
        #pragma unroll
        for (int i = 0; i < 4; i++) {
            cp16(As + s*TSZ32 + dBase + i*1024, gA + (size_t)i*32*lda + ko);
            cp16(Bs + s*TSZ32 + dBase + i*1024, gB + (size_t)i*32*ldb + ko);
        }
        cp_commit();
    }
    cp_wait1();
    __syncthreads();

    for (int kt = 0; kt < KT; kt++) {
        const int cur = kt % 3;
        if (kt + 2 < KT) {
            const int st = (kt + 2) % 3;
            const size_t ko = (size_t)(kt + 2) * 32;
            #pragma unroll
            for (int i = 0; i < 4; i++) {
                cp16(As + st*TSZ32 + dBase + i*1024, gA + (size_t)i*32*lda + ko);
                cp16(Bs + st*TSZ32 + dBase + i*1024, gB + (size_t)i*32*ldb + ko);
            }
        }
        cp_commit();

        const unsigned aOff  = aBase  + (unsigned)cur * STB;
        const unsigned bOff0 = bBase0 + (unsigned)cur * STB;
        const unsigned bOff1 = bBase1 + (unsigned)cur * STB;

        #pragma unroll
        for (int ks = 0; ks < 4; ks++) {
            unsigned af[4][4];
            unsigned bf[4][2];
            #pragma unroll
            for (int i = 0; i < 4; i++)
                ldsm4(af[i][0], af[i][1], af[i][2], af[i][3],
                      aOff + (unsigned)i*2048 + tks[ks]);
            ldsm4(bf[0][0], bf[1][0], bf[0][1], bf[1][1], bOff0 + tks[ks]);
            ldsm4(bf[2][0], bf[3][0], bf[2][1], bf[3][1], bOff1 + tks[ks]);

            #pragma unroll
            for (int i = 0; i < 4; i++)
                #pragma unroll
                for (int j = 0; j < 4; j++) {
                    asm volatile(
                        "mma.sync.aligned.m16n8k8.row.col.f32.tf32.tf32.f32 "
                        "{%0,%1,%2,%3}, {%4,%5,%6,%7}, {%8,%9}, {%0,%1,%2,%3};"
                        : "+f"(acc[i][j][0]), "+f"(acc[i][j][1]),
                          "+f"(acc[i][j][2]), "+f"(acc[i][j][3])
                        : "r"(af[i][0]), "r"(af[i][1]), "r"(af[i][2]), "r"(af[i][3]),
                          "r"(bf[j][0]), "r"(bf[j][1]));
                }
        }

        cp_wait1();
        __syncthreads();
    }

    #pragma unroll
    for (int i = 0; i < 4; i++) {
        const int r0e = bm + wm + i*16 + u;
        #pragma unroll
        for (int j = 0; j < 4; j++) {
            const int c0 = bn + wn + j*8 + li*2;
            float v0 = acc[i][j][0], v1 = acc[i][j][1];
            float v2 = acc[i][j][2], v3 = acc[i][j][3];
            if (EPI == 1) {
                const float bA = bias[c0], bB = bias[c0+1];
                v0 += bA; v1 += bB; v2 += bA; v3 += bB;
                v0 = (v0 > 20.0f) ? v0 : log1pf(__expf(v0));
                v1 = (v1 > 20.0f) ? v1 : log1pf(__expf(v1));
                v2 = (v2 > 20.0f) ? v2 : log1pf(__expf(v2));
                v3 = (v3 > 20.0f) ? v3 : log1pf(__expf(v3));
            }
            *(float2*)&C[(size_t)r0e * ldc + c0]     = make_float2(v0, v1);
            *(float2*)&C[(size_t)(r0e+8) * ldc + c0] = make_float2(v2, v3);
        }
    }
}

// ---------------- fp32 tiled SGEMM (x_proj: N=160) ----------------
template<int BM, int BN, int BK, int TM, int TN>
__global__ __launch_bounds__(256)
void sgemm_kernel(int M, int N, int K,
                  const float* __restrict__ A, int lda,
                  const float* __restrict__ Bw, int ldb,
                  float* __restrict__ C, int ldc,
                  float* __restrict__ C2)
{
    __shared__ float As[BK][BM];
    __shared__ float Bs[BK][BN];

    const int tid = threadIdx.x;
    const int tx  = tid & 15;
    const int ty  = tid >> 4;
    const int bm  = blockIdx.y * BM;
    const int bn  = blockIdx.x * BN;

    float acc[TM][TN];
    #pragma unroll
    for (int i = 0; i < TM; i++)
        #pragma unroll
        for (int j = 0; j < TN; j++) acc[i][j] = 0.0f;

    const int a_m = tid / (BK/4);
    const int a_k = (tid % (BK/4)) * 4;
    const int b_n = tid / (BK/4);
    const int b_k = (tid % (BK/4)) * 4;

    for (int k0 = 0; k0 < K; k0 += BK) {
        if (tid < (BM*BK/4)) {
            float4 v = *(const float4*)&A[(size_t)(bm + a_m)*lda + k0 + a_k];
            As[a_k+0][a_m] = v.x; As[a_k+1][a_m] = v.y;
            As[a_k+2][a_m] = v.z; As[a_k+3][a_m] = v.w;
        }
        if (tid < (BN*BK/4)) {
            float4 v = *(const float4*)&Bw[(size_t)(bn + b_n)*ldb + k0 + b_k];
            Bs[b_k+0][b_n] = v.x; Bs[b_k+1][b_n] = v.y;
            Bs[b_k+2][b_n] = v.z; Bs[b_k+3][b_n] = v.w;
        }
        __syncthreads();

        #pragma unroll
        for (int k = 0; k < BK; k++) {
            float rm[TM], rn[TN];
            #pragma unroll
            for (int i = 0; i < TM; i++) rm[i] = As[k][ty*TM + i];
            #pragma unroll
            for (int j = 0; j < TN; j++) rn[j] = Bs[k][tx*TN + j];
            #pragma unroll
            for (int i = 0; i < TM; i++)
                #pragma unroll
                for (int j = 0; j < TN; j++)
                    acc[i][j] += rm[i] * rn[j];
        }
        __syncthreads();
    }

    #pragma unroll
    for (int i = 0; i < TM; i++) {
        const int m = bm + ty*TM + i;
        #pragma unroll
        for (int j = 0; j < TN; j++) {
            const int n = bn + tx*TN + j;
            C[(size_t)m*ldc + n] = acc[i][j];
            if (C2 && n < DTR)
                C2[(size_t)m*DTR + n] = tf32r(acc[i][j]);
        }
    }
}

// ---------------- depthwise causal conv(k=4) + bias + silu, L-chunked ----------------
#define CLC 128
__global__ __launch_bounds__(256)
void conv_silu_kernel(const float* __restrict__ xz,
                      const float* __restrict__ w,
                      const float* __restrict__ bias,
                      float* __restrict__ xc)
{
    const int d  = blockIdx.x * blockDim.x + threadIdx.x;
    const int b  = blockIdx.z;
    const int l0 = blockIdx.y * CLC;

    const float w0 = w[d*4+0], w1 = w[d*4+1], w2 = w[d*4+2], w3 = w[d*4+3];
    const float bi = bias[d];
    const float* px = xz + ((size_t)b * L_ + l0) * EI + d;
    float*       po = xc + ((size_t)b * L_ + l0) * DI + d;

    float x0 = 0.f, x1 = 0.f, x2 = 0.f;
    if (l0 > 0) {
        x0 = px[-(size_t)3 * EI];
        x1 = px[-(size_t)2 * EI];
        x2 = px[-(size_t)1 * EI];
    }
    #pragma unroll 4
    for (int l = 0; l < CLC; l++) {
        float x3 = px[(size_t)l * EI];
        float v  = w0*x0 + w1*x1 + w2*x2 + w3*x3 + bi;
        v = v / (1.0f + __expf(-v));
        po[(size_t)l * DI] = v;
        x0 = x1; x1 = x2; x2 = x3;
    }
}

// ---------------- selective scan: barrier-free, BC via shfl, prefetch 2 ----------------
__global__ __launch_bounds__(64)
void scan_kernel(const float* __restrict__ xz,
                 const float* __restrict__ xc,
                 const float* __restrict__ dt,
                 const float* __restrict__ xdbl,
                 const float* __restrict__ A_log,
                 const float* __restrict__ Dp,
                 float* __restrict__ y)
{
    const int b    = blockIdx.y;
    const int d    = blockIdx.x * 64 + threadIdx.x;
    const int lane = threadIdx.x & 31;

    float negA[DS];
    #pragma unroll
    for (int n = 0; n < DS; n++) negA[n] = -__expf(A_log[d*DS + n]);

    bool chain = (negA[0] != 0.0f);
    #pragma unroll
    for (int n = 1; n < DS; n++) {
        float r = negA[n] - (float)(n+1) * negA[0];
        if (fabsf(r) > 1e-4f * fabsf(negA[n])) chain = false;
    }

    const float Dd = Dp[d];
    float h[DS];
    #pragma unroll
    for (int n = 0; n < DS; n++) h[n] = 0.0f;

    const size_t rb = (size_t)b * L_;
    const float* pdt = dt   + rb * DI + d;
    const float* pxc = xc   + rb * DI + d;
    const float* pz  = xz   + rb * EI + DI + d;
    const float* pbc = xdbl + rb * XD + DTR;   // lane -> BC[lane] (0..15 B, 16..31 C)
    float*       py  = y    + rb * DI + d;

    // prefetch l = 0, 1
    float bc0 = pbc[lane];
    float bc1 = pbc[XD + lane];
    float dt0 = pdt[0],  x0v = pxc[0],  z0v = pz[0];
    float dt1 = pdt[DI], x1v = pxc[DI], z1v = pz[EI];

    for (int l = 0; l < L_; l++) {
        float bc2 = 0.f, dt2 = 0.f, x2v = 0.f, z2v = 0.f;
        if (l + 2 < L_) {
            bc2 = pbc[(size_t)(l+2) * XD + lane];
            dt2 = pdt[(size_t)(l+2) * DI];
            x2v = pxc[(size_t)(l+2) * DI];
            z2v = pz [(size_t)(l+2) * EI];
        }

        const float dtv = dt0;
        float dA[DS];
        if (chain) {
            float base = __expf(dtv * negA[0]);
            dA[0] = base;
            dA[1] = base * base;
            #pragma unroll
            for (int n = 2; n < DS; n++)
                dA[n] = dA[(n-1) >> 1] * dA[n >> 1];
        } else {
            #pragma unroll
            for (int n = 0; n < DS; n++) dA[n] = __expf(dtv * negA[n]);
        }

        const float du = dtv * x0v;
        float yv = 0.0f;
        #pragma unroll
        for (int n = 0; n < DS; n++) {
            const float Bn = __shfl_sync(0xFFFFFFFFu, bc0, n);
            const float Cn = __shfl_sync(0xFFFFFFFFu, bc0, 16 + n);
            h[n] = h[n] * dA[n] + du * Bn;
            yv  += h[n] * Cn;
        }
        yv += x0v * Dd;
        const float zs = z0v / (1.0f + __expf(-z0v));
        py[(size_t)l * DI] = tf32r(yv * zs);

        bc0 = bc1; dt0 = dt1; x0v = x1v; z0v = z1v;
        bc1 = bc2; dt1 = dt2; x1v = x2v; z1v = z2v;
    }
}

// ---------------- launch ----------------
extern "C" void kernel_launch(void* const* d_in, const int* in_sizes, int n_in,
                              void* d_out, int out_size)
{
    const float* hs    = (const float*)d_in[0];
    const float* w_in  = (const float*)d_in[1];
    const float* convw = (const float*)d_in[2];
    const float* convb = (const float*)d_in[3];
    const float* xpw   = (const float*)d_in[4];
    const float* dtw   = (const float*)d_in[5];
    const float* dtb   = (const float*)d_in[6];
    const float* outw  = (const float*)d_in[7];
    const float* Alog  = (const float*)d_in[8];
    const float* Dp    = (const float*)d_in[9];
    float*       out   = (float*)d_out;

    float *xz, *xc, *xdbl, *dtb_, *yb;
    float *hsc, *winc, *dtwc, *outwc, *dtlo;
    cudaGetSymbolAddress((void**)&xz,    g_xz);
    cudaGetSymbolAddress((void**)&xc,    g_xc);
    cudaGetSymbolAddress((void**)&xdbl,  g_xdbl);
    cudaGetSymbolAddress((void**)&dtb_,  g_dt);
    cudaGetSymbolAddress((void**)&yb,    g_y);
    cudaGetSymbolAddress((void**)&hsc,   g_hsc);
    cudaGetSymbolAddress((void**)&winc,  g_winc);
    cudaGetSymbolAddress((void**)&dtwc,  g_dtwc);
    cudaGetSymbolAddress((void**)&outwc, g_outwc);
    cudaGetSymbolAddress((void**)&dtlo,  g_dtlo);

    const dim3 t256(256);
    const size_t msmem = 6 * TSZ32 * sizeof(float);              // 98304 (mma_gemm)
    const size_t wsmem = 3 * (TSZ_A + TSZ_B) * sizeof(float);    // 147456 (wide)

    cudaFuncSetAttribute(mma_gemm<1>,  cudaFuncAttributeMaxDynamicSharedMemorySize, (int)msmem);
    cudaFuncSetAttribute(mma_gemm_wide, cudaFuncAttributeMaxDynamicSharedMemorySize, (int)wsmem);

    // 0) pre-round GEMM operands to tf32
    {
        size_t n;
        n = (size_t)ML*DM/4;   round_tf32_kernel<<<(unsigned)((n+255)/256), t256>>>(hs,   hsc,   n);
        n = (size_t)EI*DM/4;   round_tf32_kernel<<<(unsigned)((n+255)/256), t256>>>(w_in, winc,  n);
        n = (size_t)DI*DTR/4;  round_tf32_kernel<<<(unsigned)((n+255)/256), t256>>>(dtw,  dtwc,  n);
        n = (size_t)DM*DI/4;   round_tf32_kernel<<<(unsigned)((n+255)/256), t256>>>(outw, outwc, n);
    }

    // 1) in_proj: xz[ML,EI] = hsc * winc^T   (wide mma)
    mma_gemm_wide<<<dim3(EI/256, ML/128), dim3(512), wsmem>>>(
        ML, EI, DM, hsc, DM, winc, DM, xz, EI);

    // 2) depthwise conv + silu (L-chunked)
    conv_silu_kernel<<<dim3(DI/256, L_/CLC, B_), t256>>>(xz, convw, convb, xc);

    // 3) x_proj (fp32, N=160); emits rounded compact dt_lo
    sgemm_kernel<64,32,16,4,2><<<dim3(XD/32, ML/64), t256>>>(
        ML, XD, DI, xc, DI, xpw, DI, xdbl, XD, dtlo);

    // 4) dt_proj + softplus (mma.sync tf32, BN=128)
    mma_gemm<1><<<dim3(DI/128, ML/128), t256, msmem>>>(
        ML, DI, DTR, dtlo, DTR, dtwc, DTR, dtb_, DI, dtb);

    // 5) selective scan (barrier-free, shfl BC)
    scan_kernel<<<dim3(DI/64, B_), dim3(64)>>>(
        xz, xc, dtb_, xdbl, Alog, Dp, yb);

    // 6) out_proj: out = y * outwc^T   (wide mma)
    mma_gemm_wide<<<dim3(DM/256, ML/128), dim3(512), wsmem>>>(
        ML, DM, DI, yb, DI, outwc, DI, out, DM);
}

// round 9
// speedup vs baseline: 1.5164x; 1.0234x over previous
#include <cuda_runtime.h>
#include <cstdint>
#include <cstddef>

// ---------------- problem constants ----------------
#define B_   2
#define L_   2048
#define DM   2048          // d_model
#define DI   4096          // d_inner
#define EI   8192          // 2*d_inner
#define DS   16            // d_state
#define DTR  128           // dt_rank
#define XD   160           // dt_rank + 2*d_state
#define ML   (B_*L_)       // 4096 rows

// ---------------- scratch (device globals; no allocation allowed) ----------------
__device__ float g_xz  [(size_t)ML * EI];
__device__ float g_xc  [(size_t)ML * DI];   // conv+silu (exact fp32)
__device__ float g_xcr [(size_t)ML * DI];   // conv+silu (tf32-rounded)
__device__ float g_bc  [(size_t)ML * 32];   // B(16) + C(16) per row, exact fp32
__device__ float g_dt  [(size_t)ML * DI];
__device__ float g_y   [(size_t)ML * DI];   // scan output (tf32-rounded)
__device__ float g_hsc [(size_t)ML * DM];   // tf32-rounded hidden_states
__device__ float g_winc[(size_t)EI * DM];   // tf32-rounded in_proj_weight
__device__ float g_dtwc[(size_t)DI * DTR];  // tf32-rounded dt_proj_weight
__device__ float g_outwc[(size_t)DM * DI];  // tf32-rounded out_proj_weight
__device__ float g_xpwc[(size_t)DTR * DI];  // tf32-rounded x_proj_weight rows 0..127
__device__ float g_dtlo[(size_t)ML * DTR];  // tf32 dt_lo (compact)

__device__ __forceinline__ unsigned f2tf32(float f) {
    unsigned u;
    asm("cvt.rna.tf32.f32 %0, %1;" : "=r"(u) : "f"(f));
    return u;
}
__device__ __forceinline__ float tf32r(float f) {
    return __uint_as_float(f2tf32(f));
}

// ---------------- fused tf32 rounding: 5 segments in one launch ----------------
__global__ __launch_bounds__(256)
void round_all_kernel(const float* s0, float* d0, size_t n0,
                      const float* s1, float* d1, size_t n1,
                      const float* s2, float* d2, size_t n2,
                      const float* s3, float* d3, size_t n3,
                      const float* s4, float* d4, size_t n4)
{
    size_t i = (size_t)blockIdx.x * blockDim.x + threadIdx.x;
    const float* s; float* d;
    if (i < n0) { s = s0; d = d0; }
    else if ((i -= n0) < n1) { s = s1; d = d1; }
    else if ((i -= n1) < n2) { s = s2; d = d2; }
    else if ((i -= n2) < n3) { s = s3; d = d3; }
    else if ((i -= n3) < n4) { s = s4; d = d4; }
    else return;
    float4 v = ((const float4*)s)[i];
    v.x = tf32r(v.x); v.y = tf32r(v.y); v.z = tf32r(v.z); v.w = tf32r(v.w);
    ((float4*)d)[i] = v;
}

// ---------------- async-copy + ldmatrix helpers ----------------
__device__ __forceinline__ void cp16(float* smem_dst, const float* gmem_src) {
    unsigned s = (unsigned)__cvta_generic_to_shared(smem_dst);
    asm volatile("cp.async.cg.shared.global [%0], [%1], 16;\n" :: "r"(s), "l"(gmem_src));
}
__device__ __forceinline__ void cp_commit() {
    asm volatile("cp.async.commit_group;\n");
}
__device__ __forceinline__ void cp_wait1() {
    asm volatile("cp.async.wait_group 1;\n");
}
__device__ __forceinline__ void cp_wait2() {
    asm volatile("cp.async.wait_group 2;\n");
}
__device__ __forceinline__ void ldsm4(unsigned& r0, unsigned& r1, unsigned& r2, unsigned& r3,
                                      unsigned addr) {
    asm volatile("ldmatrix.sync.aligned.m8n8.x4.shared.b16 {%0,%1,%2,%3}, [%4];"
                 : "=r"(r0), "=r"(r1), "=r"(r2), "=r"(r3) : "r"(addr));
}

// =========================================================================
// WIDE TF32 GEMM: BM=128, BN=256, BK=32, 512 threads (16 warps, 2m x 8n),
// warp tile 64x32, 4-stage cp.async (wait_group 2), ldmatrix fragments.
// =========================================================================
#define TSZ_A 4096          // floats per A stage (128*32)
#define TSZ_B 8192          // floats per B stage (256*32)
#define STB_A 16384u
#define STB_B 32768u

__global__ __launch_bounds__(512, 1)
void mma_gemm_wide(int M, int N, int K,
                   const float* __restrict__ A, int lda,
                   const float* __restrict__ Bw, int ldb,
                   float* __restrict__ C, int ldc)
{
    extern __shared__ float smem[];
    float* As = smem;               // 4 * 4096
    float* Bs = smem + 4*TSZ_A;     // 4 * 8192

    const int tid  = threadIdx.x;
    const int lane = tid & 31;
    const int warp = tid >> 5;
    const int wm   = (warp & 1) * 64;
    const int wn   = (warp >> 1) * 32;
    const int bm   = blockIdx.y * 128;
    const int bn   = blockIdx.x * 256;

    const int q     = tid & 7;
    const int r0    = tid >> 3;
    const int pq    = q ^ (r0 & 7);
    const int dBase = r0*32 + pq*4;

    const float* gA = A  + (size_t)(bm + r0) * lda + q*4;
    const float* gB = Bw + (size_t)(bn + r0) * ldb + q*4;

    const int g    = lane >> 3;
    const int kg   = g >> 1;
    const int sub8 = (g & 1) << 3;
    const int lr   = lane & 7;
    const unsigned aSh = (unsigned)__cvta_generic_to_shared(As);
    const unsigned bSh = (unsigned)__cvta_generic_to_shared(Bs);
    const unsigned aBase  = aSh + (unsigned)(wm + sub8 + lr) * 128;
    const unsigned bBase0 = bSh + (unsigned)(wn + sub8 + lr) * 128;
    const unsigned bBase1 = bBase0 + 16*128;
    unsigned tks[4];
    #pragma unroll
    for (int ks = 0; ks < 4; ks++)
        tks[ks] = (unsigned)(((((ks << 1) + kg) ^ lr) & 7) << 4);

    const int u  = lane >> 2;
    const int li = lane & 3;

    float acc[4][4][4];
    #pragma unroll
    for (int i = 0; i < 4; i++)
        #pragma unroll
        for (int j = 0; j < 4; j++)
            #pragma unroll
            for (int r = 0; r < 4; r++) acc[i][j][r] = 0.0f;

    const int KT = K / 32;

    // ---- prologue: stages 0,1 ----
    #pragma unroll
    for (int s = 0; s < 2; s++) {
        const size_t ko = (size_t)s * 32;
        #pragma unroll
        for (int i = 0; i < 2; i++)
            cp16(As + s*TSZ_A + dBase + i*2048, gA + (size_t)i*64*lda + ko);
        #pragma unroll
        for (int i = 0; i < 4; i++)
            cp16(Bs + s*TSZ_B + dBase + i*2048, gB + (size_t)i*64*ldb + ko);
        cp_commit();
    }

    for (int kt = 0; kt < KT; kt++) {
        const int cur = kt & 3;
        // issue loads for stage kt+2 (safe: no warp reads (kt+2)&3 now)
        if (kt + 2 < KT) {
            const int st = (kt + 2) & 3;
            const size_t ko = (size_t)(kt + 2) * 32;
            #pragma unroll
            for (int i = 0; i < 2; i++)
                cp16(As + st*TSZ_A + dBase + i*2048, gA + (size_t)i*64*lda + ko);
            #pragma unroll
            for (int i = 0; i < 4; i++)
                cp16(Bs + st*TSZ_B + dBase + i*2048, gB + (size_t)i*64*ldb + ko);
        }
        cp_commit();
        cp_wait2();           // stage kt retired (2 groups may stay in flight)
        __syncthreads();      // publish to all warps

        const unsigned aOff  = aBase  + (unsigned)cur * STB_A;
        const unsigned bOff0 = bBase0 + (unsigned)cur * STB_B;
        const unsigned bOff1 = bBase1 + (unsigned)cur * STB_B;

        #pragma unroll
        for (int ks = 0; ks < 4; ks++) {
            unsigned af[4][4];
            unsigned bf[4][2];
            #pragma unroll
            for (int i = 0; i < 4; i++)
                ldsm4(af[i][0], af[i][1], af[i][2], af[i][3],
                      aOff + (unsigned)i*2048 + tks[ks]);
            ldsm4(bf[0][0], bf[1][0], bf[0][1], bf[1][1], bOff0 + tks[ks]);
            ldsm4(bf[2][0], bf[3][0], bf[2][1], bf[3][1], bOff1 + tks[ks]);

            #pragma unroll
            for (int i = 0; i < 4; i++)
                #pragma unroll
                for (int j = 0; j < 4; j++) {
                    asm volatile(
                        "mma.sync.aligned.m16n8k8.row.col.f32.tf32.tf32.f32 "
                        "{%0,%1,%2,%3}, {%4,%5,%6,%7}, {%8,%9}, {%0,%1,%2,%3};"
                        : "+f"(acc[i][j][0]), "+f"(acc[i][j][1]),
                          "+f"(acc[i][j][2]), "+f"(acc[i][j][3])
                        : "r"(af[i][0]), "r"(af[i][1]), "r"(af[i][2]), "r"(af[i][3]),
                          "r"(bf[j][0]), "r"(bf[j][1]));
                }
        }
    }

    #pragma unroll
    for (int i = 0; i < 4; i++) {
        const int r0e = bm + wm + i*16 + u;
        #pragma unroll
        for (int j = 0; j < 4; j++) {
            const int c0 = bn + wn + j*8 + li*2;
            *(float2*)&C[(size_t)r0e * ldc + c0]     = make_float2(acc[i][j][0], acc[i][j][1]);
            *(float2*)&C[(size_t)(r0e+8) * ldc + c0] = make_float2(acc[i][j][2], acc[i][j][3]);
        }
    }
}

// ================= mma.sync TF32 GEMM BN=128 =================
// EPI: 0 = none, 1 = softplus(v+bias[n]), 2 = tf32-round output
#define TSZ32 4096
#define STB   16384u

template<int EPI>
__global__ __launch_bounds__(256, 2)
void mma_gemm(int M, int N, int K,
              const float* __restrict__ A, int lda,
              const float* __restrict__ Bw, int ldb,
              float* __restrict__ C, int ldc,
              const float* __restrict__ bias)
{
    extern __shared__ float smem[];
    float* As = smem;
    float* Bs = smem + 3*TSZ32;

    const int tid  = threadIdx.x;
    const int lane = tid & 31;
    const int warp = tid >> 5;
    const int wm   = (warp & 1) * 64;
    const int wn   = (warp >> 1) * 32;
    const int bm   = blockIdx.y * 128;
    const int bn   = blockIdx.x * 128;

    const int q     = tid & 7;
    const int r0    = tid >> 3;
    const int pq    = q ^ (r0 & 7);
    const int dBase = r0*32 + pq*4;

    const float* gA = A  + (size_t)(bm + r0) * lda + q*4;
    const float* gB = Bw + (size_t)(bn + r0) * ldb + q*4;

    const int g    = lane >> 3;
    const int kg   = g >> 1;
    const int sub8 = (g & 1) << 3;
    const int lr   = lane & 7;
    const unsigned aSh = (unsigned)__cvta_generic_to_shared(As);
    const unsigned bSh = (unsigned)__cvta_generic_to_shared(Bs);
    const unsigned aBase  = aSh + (unsigned)(wm + sub8 + lr) * 128;
    const unsigned bBase0 = bSh + (unsigned)(wn + sub8 + lr) * 128;
    const unsigned bBase1 = bBase0 + 16*128;
    unsigned tks[4];
    #pragma unroll
    for (int ks = 0; ks < 4; ks++)
        tks[ks] = (unsigned)(((((ks << 1) + kg) ^ lr) & 7) << 4);

    const int u  = lane >> 2;
    const int li = lane & 3;

    float acc[4][4][4];
    #pragma unroll
    for (int i = 0; i < 4; i++)
        #pragma unroll
        for (int j = 0; j < 4; j++)
            #pragma unroll
            for (int r = 0; r < 4; r++) acc[i][j][r] = 0.0f;

    const int KT = K / 32;

    #pragma unroll
    for (int s = 0; s < 2; s++) {
        const size_t ko = (size_t)s * 32;
        #pragma unroll
        for (int i = 0; i < 4; i++) {
            cp16(As + s*TSZ32 + dBase + i*1024, gA + (size_t)i*32*lda + ko);
            cp16(Bs + s*TSZ32 + dBase + i*1024, gB + (size_t)i*32*ldb + ko);
        }
        cp_commit();
    }
    cp_wait1();
    __syncthreads();

    for (int kt = 0; kt < KT; kt++) {
        const int cur = kt % 3;
        if (kt + 2 < KT) {
            const int st = (kt + 2) % 3;
            const size_t ko = (size_t)(kt + 2) * 32;
            #pragma unroll
            for (int i = 0; i < 4; i++) {
                cp16(As + st*TSZ32 + dBase + i*1024, gA + (size_t)i*32*lda + ko);
                cp16(Bs + st*TSZ32 + dBase + i*1024, gB + (size_t)i*32*ldb + ko);
            }
        }
        cp_commit();

        const unsigned aOff  = aBase  + (unsigned)cur * STB;
        const unsigned bOff0 = bBase0 + (unsigned)cur * STB;
        const unsigned bOff1 = bBase1 + (unsigned)cur * STB;

        #pragma unroll
        for (int ks = 0; ks < 4; ks++) {
            unsigned af[4][4];
            unsigned bf[4][2];
            #pragma unroll
            for (int i = 0; i < 4; i++)
                ldsm4(af[i][0], af[i][1], af[i][2], af[i][3],
                      aOff + (unsigned)i*2048 + tks[ks]);
            ldsm4(bf[0][0], bf[1][0], bf[0][1], bf[1][1], bOff0 + tks[ks]);
            ldsm4(bf[2][0], bf[3][0], bf[2][1], bf[3][1], bOff1 + tks[ks]);

            #pragma unroll
            for (int i = 0; i < 4; i++)
                #pragma unroll
                for (int j = 0; j < 4; j++) {
                    asm volatile(
                        "mma.sync.aligned.m16n8k8.row.col.f32.tf32.tf32.f32 "
                        "{%0,%1,%2,%3}, {%4,%5,%6,%7}, {%8,%9}, {%0,%1,%2,%3};"
                        : "+f"(acc[i][j][0]), "+f"(acc[i][j][1]),
                          "+f"(acc[i][j][2]), "+f"(acc[i][j][3])
                        : "r"(af[i][0]), "r"(af[i][1]), "r"(af[i][2]), "r"(af[i][3]),
                          "r"(bf[j][0]), "r"(bf[j][1]));
                }
        }

        cp_wait1();
        __syncthreads();
    }

    #pragma unroll
    for (int i = 0; i < 4; i++) {
        const int r0e = bm + wm + i*16 + u;
        #pragma unroll
        for (int j = 0; j < 4; j++) {
            const int c0 = bn + wn + j*8 + li*2;
            float v0 = acc[i][j][0], v1 = acc[i][j][1];
            float v2 = acc[i][j][2], v3 = acc[i][j][3];
            if (EPI == 1) {
                const float bA = bias[c0], bB = bias[c0+1];
                v0 += bA; v1 += bB; v2 += bA; v3 += bB;
                v0 = (v0 > 20.0f) ? v0 : log1pf(__expf(v0));
                v1 = (v1 > 20.0f) ? v1 : log1pf(__expf(v1));
                v2 = (v2 > 20.0f) ? v2 : log1pf(__expf(v2));
                v3 = (v3 > 20.0f) ? v3 : log1pf(__expf(v3));
            }
            if (EPI == 2) {
                v0 = tf32r(v0); v1 = tf32r(v1); v2 = tf32r(v2); v3 = tf32r(v3);
            }
            *(float2*)&C[(size_t)r0e * ldc + c0]     = make_float2(v0, v1);
            *(float2*)&C[(size_t)(r0e+8) * ldc + c0] = make_float2(v2, v3);
        }
    }
}

// ---------------- fp32 tiled SGEMM (B/C part of x_proj: N=32) ----------------
template<int BM, int BN, int BK, int TM, int TN>
__global__ __launch_bounds__(256)
void sgemm_kernel(int M, int N, int K,
                  const float* __restrict__ A, int lda,
                  const float* __restrict__ Bw, int ldb,
                  float* __restrict__ C, int ldc)
{
    __shared__ float As[BK][BM];
    __shared__ float Bs[BK][BN];

    const int tid = threadIdx.x;
    const int tx  = tid & 15;
    const int ty  = tid >> 4;
    const int bm  = blockIdx.y * BM;
    const int bn  = blockIdx.x * BN;

    float acc[TM][TN];
    #pragma unroll
    for (int i = 0; i < TM; i++)
        #pragma unroll
        for (int j = 0; j < TN; j++) acc[i][j] = 0.0f;

    const int a_m = tid / (BK/4);
    const int a_k = (tid % (BK/4)) * 4;
    const int b_n = tid / (BK/4);
    const int b_k = (tid % (BK/4)) * 4;

    for (int k0 = 0; k0 < K; k0 += BK) {
        if (tid < (BM*BK/4)) {
            float4 v = *(const float4*)&A[(size_t)(bm + a_m)*lda + k0 + a_k];
            As[a_k+0][a_m] = v.x; As[a_k+1][a_m] = v.y;
            As[a_k+2][a_m] = v.z; As[a_k+3][a_m] = v.w;
        }
        if (tid < (BN*BK/4)) {
            float4 v = *(const float4*)&Bw[(size_t)(bn + b_n)*ldb + k0 + b_k];
            Bs[b_k+0][b_n] = v.x; Bs[b_k+1][b_n] = v.y;
            Bs[b_k+2][b_n] = v.z; Bs[b_k+3][b_n] = v.w;
        }
        __syncthreads();

        #pragma unroll
        for (int k = 0; k < BK; k++) {
            float rm[TM], rn[TN];
            #pragma unroll
            for (int i = 0; i < TM; i++) rm[i] = As[k][ty*TM + i];
            #pragma unroll
            for (int j = 0; j < TN; j++) rn[j] = Bs[k][tx*TN + j];
            #pragma unroll
            for (int i = 0; i < TM; i++)
                #pragma unroll
                for (int j = 0; j < TN; j++)
                    acc[i][j] += rm[i] * rn[j];
        }
        __syncthreads();
    }

    #pragma unroll
    for (int i = 0; i < TM; i++) {
        const int m = bm + ty*TM + i;
        #pragma unroll
        for (int j = 0; j < TN; j++) {
            const int n = bn + tx*TN + j;
            C[(size_t)m*ldc + n] = acc[i][j];
        }
    }
}

// ---------------- depthwise causal conv(k=4) + bias + silu, L-chunked ----------------
// writes exact xc AND tf32-rounded xcr
#define CLC 128
__global__ __launch_bounds__(256)
void conv_silu_kernel(const float* __restrict__ xz,
                      const float* __restrict__ w,
                      const float* __restrict__ bias,
                      float* __restrict__ xc,
                      float* __restrict__ xcr)
{
    const int d  = blockIdx.x * blockDim.x + threadIdx.x;
    const int b  = blockIdx.z;
    const int l0 = blockIdx.y * CLC;

    const float w0 = w[d*4+0], w1 = w[d*4+1], w2 = w[d*4+2], w3 = w[d*4+3];
    const float bi = bias[d];
    const float* px = xz  + ((size_t)b * L_ + l0) * EI + d;
    float*       po = xc  + ((size_t)b * L_ + l0) * DI + d;
    float*       pr = xcr + ((size_t)b * L_ + l0) * DI + d;

    float x0 = 0.f, x1 = 0.f, x2 = 0.f;
    if (l0 > 0) {
        x0 = px[-(size_t)3 * EI];
        x1 = px[-(size_t)2 * EI];
        x2 = px[-(size_t)1 * EI];
    }
    #pragma unroll 4
    for (int l = 0; l < CLC; l++) {
        float x3 = px[(size_t)l * EI];
        float v  = w0*x0 + w1*x1 + w2*x2 + w3*x3 + bi;
        v = v / (1.0f + __expf(-v));
        po[(size_t)l * DI] = v;
        pr[(size_t)l * DI] = tf32r(v);
        x0 = x1; x1 = x2; x2 = x3;
    }
}

// ---------------- selective scan: barrier-free, BC via shfl, prefetch 2 ----------------
__global__ __launch_bounds__(64)
void scan_kernel(const float* __restrict__ xz,
                 const float* __restrict__ xc,
                 const float* __restrict__ dt,
                 const float* __restrict__ bc,     // [ML,32]: B 0..15, C 16..31
                 const float* __restrict__ A_log,
                 const float* __restrict__ Dp,
                 float* __restrict__ y)
{
    const int b    = blockIdx.y;
    const int d    = blockIdx.x * 64 + threadIdx.x;
    const int lane = threadIdx.x & 31;

    float negA[DS];
    #pragma unroll
    for (int n = 0; n < DS; n++) negA[n] = -__expf(A_log[d*DS + n]);

    bool chain = (negA[0] != 0.0f);
    #pragma unroll
    for (int n = 1; n < DS; n++) {
        float r = negA[n] - (float)(n+1) * negA[0];
        if (fabsf(r) > 1e-4f * fabsf(negA[n])) chain = false;
    }

    const float Dd = Dp[d];
    float h[DS];
    #pragma unroll
    for (int n = 0; n < DS; n++) h[n] = 0.0f;

    const size_t rb = (size_t)b * L_;
    const float* pdt = dt + rb * DI + d;
    const float* pxc = xc + rb * DI + d;
    const float* pz  = xz + rb * EI + DI + d;
    const float* pbc = bc + rb * 32;
    float*       py  = y  + rb * DI + d;

    float bc0 = pbc[lane];
    float bc1 = pbc[32 + lane];
    float dt0 = pdt[0],  x0v = pxc[0],  z0v = pz[0];
    float dt1 = pdt[DI], x1v = pxc[DI], z1v = pz[EI];

    for (int l = 0; l < L_; l++) {
        float bc2 = 0.f, dt2 = 0.f, x2v = 0.f, z2v = 0.f;
        if (l + 2 < L_) {
            bc2 = pbc[(size_t)(l+2) * 32 + lane];
            dt2 = pdt[(size_t)(l+2) * DI];
            x2v = pxc[(size_t)(l+2) * DI];
            z2v = pz [(size_t)(l+2) * EI];
        }

        const float dtv = dt0;
        float dA[DS];
        if (chain) {
            float base = __expf(dtv * negA[0]);
            dA[0] = base;
            dA[1] = base * base;
            #pragma unroll
            for (int n = 2; n < DS; n++)
                dA[n] = dA[(n-1) >> 1] * dA[n >> 1];
        } else {
            #pragma unroll
            for (int n = 0; n < DS; n++) dA[n] = __expf(dtv * negA[n]);
        }

        const float du = dtv * x0v;
        float yv = 0.0f;
        #pragma unroll
        for (int n = 0; n < DS; n++) {
            const float Bn = __shfl_sync(0xFFFFFFFFu, bc0, n);
            const float Cn = __shfl_sync(0xFFFFFFFFu, bc0, 16 + n);
            h[n] = h[n] * dA[n] + du * Bn;
            yv  += h[n] * Cn;
        }
        yv += x0v * Dd;
        const float zs = z0v / (1.0f + __expf(-z0v));
        py[(size_t)l * DI] = tf32r(yv * zs);

        bc0 = bc1; dt0 = dt1; x0v = x1v; z0v = z1v;
        bc1 = bc2; dt1 = dt2; x1v = x2v; z1v = z2v;
    }
}

// ---------------- launch ----------------
extern "C" void kernel_launch(void* const* d_in, const int* in_sizes, int n_in,
                              void* d_out, int out_size)
{
    const float* hs    = (const float*)d_in[0];
    const float* w_in  = (const float*)d_in[1];
    const float* convw = (const float*)d_in[2];
    const float* convb = (const float*)d_in[3];
    const float* xpw   = (const float*)d_in[4];
    const float* dtw   = (const float*)d_in[5];
    const float* dtb   = (const float*)d_in[6];
    const float* outw  = (const float*)d_in[7];
    const float* Alog  = (const float*)d_in[8];
    const float* Dp    = (const float*)d_in[9];
    float*       out   = (float*)d_out;

    float *xz, *xc, *xcr, *bc, *dtb_, *yb;
    float *hsc, *winc, *dtwc, *outwc, *xpwc, *dtlo;
    cudaGetSymbolAddress((void**)&xz,    g_xz);
    cudaGetSymbolAddress((void**)&xc,    g_xc);
    cudaGetSymbolAddress((void**)&xcr,   g_xcr);
    cudaGetSymbolAddress((void**)&bc,    g_bc);
    cudaGetSymbolAddress((void**)&dtb_,  g_dt);
    cudaGetSymbolAddress((void**)&yb,    g_y);
    cudaGetSymbolAddress((void**)&hsc,   g_hsc);
    cudaGetSymbolAddress((void**)&winc,  g_winc);
    cudaGetSymbolAddress((void**)&dtwc,  g_dtwc);
    cudaGetSymbolAddress((void**)&outwc, g_outwc);
    cudaGetSymbolAddress((void**)&xpwc,  g_xpwc);
    cudaGetSymbolAddress((void**)&dtlo,  g_dtlo);

    const dim3 t256(256);
    const size_t msmem = 6 * TSZ32 * sizeof(float);              // 98304 (mma_gemm)
    const size_t wsmem = 4 * (TSZ_A + TSZ_B) * sizeof(float);    // 196608 (wide)

    cudaFuncSetAttribute(mma_gemm<1>,   cudaFuncAttributeMaxDynamicSharedMemorySize, (int)msmem);
    cudaFuncSetAttribute(mma_gemm<2>,   cudaFuncAttributeMaxDynamicSharedMemorySize, (int)msmem);
    cudaFuncSetAttribute(mma_gemm_wide, cudaFuncAttributeMaxDynamicSharedMemorySize, (int)wsmem);

    // 0) fused tf32 pre-rounding: hs, w_in, dtw, outw, xpw[0:128] rows
    {
        const size_t n0 = (size_t)ML*DM/4, n1 = (size_t)EI*DM/4,
                     n2 = (size_t)DI*DTR/4, n3 = (size_t)DM*DI/4,
                     n4 = (size_t)DTR*DI/4;
        const size_t nt = n0 + n1 + n2 + n3 + n4;
        round_all_kernel<<<(unsigned)((nt+255)/256), t256>>>(
            hs, hsc, n0, w_in, winc, n1, dtw, dtwc, n2, outw, outwc, n3, xpw, xpwc, n4);
    }

    // 1) in_proj (wide tf32 mma)
    mma_gemm_wide<<<dim3(EI/256, ML/128), dim3(512), wsmem>>>(
        ML, EI, DM, hsc, DM, winc, DM, xz, EI);

    // 2) depthwise conv + silu (writes exact xc + rounded xcr)
    conv_silu_kernel<<<dim3(DI/256, L_/CLC, B_), t256>>>(xz, convw, convb, xc, xcr);

    // 3a) x_proj B/C part (fp32 exact, N=32)
    sgemm_kernel<64,32,16,4,2><<<dim3(1, ML/64), t256>>>(
        ML, 32, DI, xc, DI, xpw + (size_t)DTR*DI, DI, bc, 32);

    // 3b) x_proj dt_lo part (tf32 mma, output tf32-rounded)
    mma_gemm<2><<<dim3(1, ML/128), t256, msmem>>>(
        ML, DTR, DI, xcr, DI, xpwc, DI, dtlo, DTR, nullptr);

    // 4) dt_proj + softplus (tf32 mma)
    mma_gemm<1><<<dim3(DI/128, ML/128), t256, msmem>>>(
        ML, DI, DTR, dtlo, DTR, dtwc, DTR, dtb_, DI, dtb);

    // 5) selective scan
    scan_kernel<<<dim3(DI/64, B_), dim3(64)>>>(
        xz, xc, dtb_, bc, Alog, Dp, yb);

    // 6) out_proj (wide tf32 mma)
    mma_gemm_wide<<<dim3(DM/256, ML/128), dim3(512), wsmem>>>(
        ML, DM, DI, yb, DI, outwc, DI, out, DM);
}

// round 10
// speedup vs baseline: 1.6684x; 1.1003x over previous
#include <cuda_runtime.h>
#include <cstdint>
#include <cstddef>

// ---------------- problem constants ----------------
#define B_   2
#define L_   2048
#define DM   2048          // d_model
#define DI   4096          // d_inner
#define EI   8192          // 2*d_inner
#define DS   16            // d_state
#define DTR  128           // dt_rank
#define XD   160           // dt_rank + 2*d_state
#define ML   (B_*L_)       // 4096 rows

#define KS_BC 8            // split-K for B/C sgemm
#define KS_DT 4            // split-K for dt_lo mma

// ---------------- scratch (device globals; no allocation allowed) ----------------
__device__ float g_xz  [(size_t)ML * EI];
__device__ float g_xc  [(size_t)ML * DI];   // conv+silu (exact fp32)
__device__ float g_xcr [(size_t)ML * DI];   // conv+silu (tf32-rounded)
__device__ float g_bc  [(size_t)ML * 32];   // B(16) + C(16) per row, fp32
__device__ float g_bcp [(size_t)KS_BC * ML * 32];   // split-K partials
__device__ float g_dt  [(size_t)ML * DI];
__device__ float g_y   [(size_t)ML * DI];   // scan output (tf32-rounded)
__device__ float g_hsc [(size_t)ML * DM];   // tf32-rounded hidden_states
__device__ float g_winc[(size_t)EI * DM];   // tf32-rounded in_proj_weight
__device__ float g_dtwc[(size_t)DI * DTR];  // tf32-rounded dt_proj_weight
__device__ float g_outwc[(size_t)DM * DI];  // tf32-rounded out_proj_weight
__device__ float g_xpwc[(size_t)DTR * DI];  // tf32-rounded x_proj_weight rows 0..127
__device__ float g_dtlo[(size_t)ML * DTR];  // tf32 dt_lo (compact)
__device__ float g_dtlp[(size_t)KS_DT * ML * DTR];  // split-K partials

__device__ __forceinline__ unsigned f2tf32(float f) {
    unsigned u;
    asm("cvt.rna.tf32.f32 %0, %1;" : "=r"(u) : "f"(f));
    return u;
}
__device__ __forceinline__ float tf32r(float f) {
    return __uint_as_float(f2tf32(f));
}

// ---------------- fused tf32 rounding: 5 segments in one launch ----------------
__global__ __launch_bounds__(256)
void round_all_kernel(const float* s0, float* d0, size_t n0,
                      const float* s1, float* d1, size_t n1,
                      const float* s2, float* d2, size_t n2,
                      const float* s3, float* d3, size_t n3,
                      const float* s4, float* d4, size_t n4)
{
    size_t i = (size_t)blockIdx.x * blockDim.x + threadIdx.x;
    const float* s; float* d;
    if (i < n0) { s = s0; d = d0; }
    else if ((i -= n0) < n1) { s = s1; d = d1; }
    else if ((i -= n1) < n2) { s = s2; d = d2; }
    else if ((i -= n2) < n3) { s = s3; d = d3; }
    else if ((i -= n3) < n4) { s = s4; d = d4; }
    else return;
    float4 v = ((const float4*)s)[i];
    v.x = tf32r(v.x); v.y = tf32r(v.y); v.z = tf32r(v.z); v.w = tf32r(v.w);
    ((float4*)d)[i] = v;
}

// ---------------- split-K reduce: bc (8 partials) + dtlo (4 partials, tf32r) ----------------
__global__ __launch_bounds__(256)
void reduce_splitk_kernel(const float* __restrict__ bcp, float* __restrict__ bc,
                          const float* __restrict__ dtlp, float* __restrict__ dtlo)
{
    const size_t nBC = (size_t)ML * 32 / 4;
    const size_t nDT = (size_t)ML * DTR / 4;
    size_t i = (size_t)blockIdx.x * blockDim.x + threadIdx.x;
    if (i < nBC) {
        float4 a = ((const float4*)bcp)[i];
        #pragma unroll
        for (int s = 1; s < KS_BC; s++) {
            float4 p = ((const float4*)(bcp + (size_t)s * ML * 32))[i];
            a.x += p.x; a.y += p.y; a.z += p.z; a.w += p.w;
        }
        ((float4*)bc)[i] = a;
    } else if ((i -= nBC) < nDT) {
        float4 a = ((const float4*)dtlp)[i];
        #pragma unroll
        for (int s = 1; s < KS_DT; s++) {
            float4 p = ((const float4*)(dtlp + (size_t)s * ML * DTR))[i];
            a.x += p.x; a.y += p.y; a.z += p.z; a.w += p.w;
        }
        a.x = tf32r(a.x); a.y = tf32r(a.y); a.z = tf32r(a.z); a.w = tf32r(a.w);
        ((float4*)dtlo)[i] = a;
    }
}

// ---------------- async-copy + ldmatrix helpers ----------------
__device__ __forceinline__ void cp16(float* smem_dst, const float* gmem_src) {
    unsigned s = (unsigned)__cvta_generic_to_shared(smem_dst);
    asm volatile("cp.async.cg.shared.global [%0], [%1], 16;\n" :: "r"(s), "l"(gmem_src));
}
__device__ __forceinline__ void cp_commit() {
    asm volatile("cp.async.commit_group;\n");
}
__device__ __forceinline__ void cp_wait1() {
    asm volatile("cp.async.wait_group 1;\n");
}
__device__ __forceinline__ void cp_wait2() {
    asm volatile("cp.async.wait_group 2;\n");
}
__device__ __forceinline__ void ldsm4(unsigned& r0, unsigned& r1, unsigned& r2, unsigned& r3,
                                      unsigned addr) {
    asm volatile("ldmatrix.sync.aligned.m8n8.x4.shared.b16 {%0,%1,%2,%3}, [%4];"
                 : "=r"(r0), "=r"(r1), "=r"(r2), "=r"(r3) : "r"(addr));
}

// =========================================================================
// WIDE TF32 GEMM: BM=128, BN=256, BK=32, 512 threads (16 warps, 2m x 8n),
// warp tile 64x32, 4-stage cp.async (wait_group 2), ldmatrix fragments.
// =========================================================================
#define TSZ_A 4096
#define TSZ_B 8192
#define STB_A 16384u
#define STB_B 32768u

__global__ __launch_bounds__(512, 1)
void mma_gemm_wide(int M, int N, int K,
                   const float* __restrict__ A, int lda,
                   const float* __restrict__ Bw, int ldb,
                   float* __restrict__ C, int ldc)
{
    extern __shared__ float smem[];
    float* As = smem;
    float* Bs = smem + 4*TSZ_A;

    const int tid  = threadIdx.x;
    const int lane = tid & 31;
    const int warp = tid >> 5;
    const int wm   = (warp & 1) * 64;
    const int wn   = (warp >> 1) * 32;
    const int bm   = blockIdx.y * 128;
    const int bn   = blockIdx.x * 256;

    const int q     = tid & 7;
    const int r0    = tid >> 3;
    const int pq    = q ^ (r0 & 7);
    const int dBase = r0*32 + pq*4;

    const float* gA = A  + (size_t)(bm + r0) * lda + q*4;
    const float* gB = Bw + (size_t)(bn + r0) * ldb + q*4;

    const int g    = lane >> 3;
    const int kg   = g >> 1;
    const int sub8 = (g & 1) << 3;
    const int lr   = lane & 7;
    const unsigned aSh = (unsigned)__cvta_generic_to_shared(As);
    const unsigned bSh = (unsigned)__cvta_generic_to_shared(Bs);
    const unsigned aBase  = aSh + (unsigned)(wm + sub8 + lr) * 128;
    const unsigned bBase0 = bSh + (unsigned)(wn + sub8 + lr) * 128;
    const unsigned bBase1 = bBase0 + 16*128;
    unsigned tks[4];
    #pragma unroll
    for (int ks = 0; ks < 4; ks++)
        tks[ks] = (unsigned)(((((ks << 1) + kg) ^ lr) & 7) << 4);

    const int u  = lane >> 2;
    const int li = lane & 3;

    float acc[4][4][4];
    #pragma unroll
    for (int i = 0; i < 4; i++)
        #pragma unroll
        for (int j = 0; j < 4; j++)
            #pragma unroll
            for (int r = 0; r < 4; r++) acc[i][j][r] = 0.0f;

    const int KT = K / 32;

    #pragma unroll
    for (int s = 0; s < 2; s++) {
        const size_t ko = (size_t)s * 32;
        #pragma unroll
        for (int i = 0; i < 2; i++)
            cp16(As + s*TSZ_A + dBase + i*2048, gA + (size_t)i*64*lda + ko);
        #pragma unroll
        for (int i = 0; i < 4; i++)
            cp16(Bs + s*TSZ_B + dBase + i*2048, gB + (size_t)i*64*ldb + ko);
        cp_commit();
    }

    for (int kt = 0; kt < KT; kt++) {
        const int cur = kt & 3;
        if (kt + 2 < KT) {
            const int st = (kt + 2) & 3;
            const size_t ko = (size_t)(kt + 2) * 32;
            #pragma unroll
            for (int i = 0; i < 2; i++)
                cp16(As + st*TSZ_A + dBase + i*2048, gA + (size_t)i*64*lda + ko);
            #pragma unroll
            for (int i = 0; i < 4; i++)
                cp16(Bs + st*TSZ_B + dBase + i*2048, gB + (size_t)i*64*ldb + ko);
        }
        cp_commit();
        cp_wait2();
        __syncthreads();

        const unsigned aOff  = aBase  + (unsigned)cur * STB_A;
        const unsigned bOff0 = bBase0 + (unsigned)cur * STB_B;
        const unsigned bOff1 = bBase1 + (unsigned)cur * STB_B;

        #pragma unroll
        for (int ks = 0; ks < 4; ks++) {
            unsigned af[4][4];
            unsigned bf[4][2];
            #pragma unroll
            for (int i = 0; i < 4; i++)
                ldsm4(af[i][0], af[i][1], af[i][2], af[i][3],
                      aOff + (unsigned)i*2048 + tks[ks]);
            ldsm4(bf[0][0], bf[1][0], bf[0][1], bf[1][1], bOff0 + tks[ks]);
            ldsm4(bf[2][0], bf[3][0], bf[2][1], bf[3][1], bOff1 + tks[ks]);

            #pragma unroll
            for (int i = 0; i < 4; i++)
                #pragma unroll
                for (int j = 0; j < 4; j++) {
                    asm volatile(
                        "mma.sync.aligned.m16n8k8.row.col.f32.tf32.tf32.f32 "
                        "{%0,%1,%2,%3}, {%4,%5,%6,%7}, {%8,%9}, {%0,%1,%2,%3};"
                        : "+f"(acc[i][j][0]), "+f"(acc[i][j][1]),
                          "+f"(acc[i][j][2]), "+f"(acc[i][j][3])
                        : "r"(af[i][0]), "r"(af[i][1]), "r"(af[i][2]), "r"(af[i][3]),
                          "r"(bf[j][0]), "r"(bf[j][1]));
                }
        }
    }

    #pragma unroll
    for (int i = 0; i < 4; i++) {
        const int r0e = bm + wm + i*16 + u;
        #pragma unroll
        for (int j = 0; j < 4; j++) {
            const int c0 = bn + wn + j*8 + li*2;
            *(float2*)&C[(size_t)r0e * ldc + c0]     = make_float2(acc[i][j][0], acc[i][j][1]);
            *(float2*)&C[(size_t)(r0e+8) * ldc + c0] = make_float2(acc[i][j][2], acc[i][j][3]);
        }
    }
}

// ================= mma.sync TF32 GEMM BN=128 =================
// EPI: 0 = none, 1 = softplus(v+bias[n])
// SPLITK: blockIdx.x = k-split index (N must be 128); partial -> C + split*M*ldc
#define TSZ32 4096
#define STB   16384u

template<int EPI, int SPLITK>
__global__ __launch_bounds__(256, 2)
void mma_gemm(int M, int N, int K,
              const float* __restrict__ A, int lda,
              const float* __restrict__ Bw, int ldb,
              float* __restrict__ C, int ldc,
              const float* __restrict__ bias)
{
    extern __shared__ float smem[];
    float* As = smem;
    float* Bs = smem + 3*TSZ32;

    const int tid  = threadIdx.x;
    const int lane = tid & 31;
    const int warp = tid >> 5;
    const int wm   = (warp & 1) * 64;
    const int wn   = (warp >> 1) * 32;
    const int bm   = blockIdx.y * 128;
    int bn = 0;
    if (SPLITK) {
        const int sk = blockIdx.x;          // k-split index
        A  += (size_t)sk * K;               // K = chunk length
        Bw += (size_t)sk * K;
        C  += (size_t)sk * M * ldc;
    } else {
        bn = blockIdx.x * 128;
    }

    const int q     = tid & 7;
    const int r0    = tid >> 3;
    const int pq    = q ^ (r0 & 7);
    const int dBase = r0*32 + pq*4;

    const float* gA = A  + (size_t)(bm + r0) * lda + q*4;
    const float* gB = Bw + (size_t)(bn + r0) * ldb + q*4;

    const int g    = lane >> 3;
    const int kg   = g >> 1;
    const int sub8 = (g & 1) << 3;
    const int lr   = lane & 7;
    const unsigned aSh = (unsigned)__cvta_generic_to_shared(As);
    const unsigned bSh = (unsigned)__cvta_generic_to_shared(Bs);
    const unsigned aBase  = aSh + (unsigned)(wm + sub8 + lr) * 128;
    const unsigned bBase0 = bSh + (unsigned)(wn + sub8 + lr) * 128;
    const unsigned bBase1 = bBase0 + 16*128;
    unsigned tks[4];
    #pragma unroll
    for (int ks = 0; ks < 4; ks++)
        tks[ks] = (unsigned)(((((ks << 1) + kg) ^ lr) & 7) << 4);

    const int u  = lane >> 2;
    const int li = lane & 3;

    float acc[4][4][4];
    #pragma unroll
    for (int i = 0; i < 4; i++)
        #pragma unroll
        for (int j = 0; j < 4; j++)
            #pragma unroll
            for (int r = 0; r < 4; r++) acc[i][j][r] = 0.0f;

    const int KT = K / 32;

    #pragma unroll
    for (int s = 0; s < 2; s++) {
        const size_t ko = (size_t)s * 32;
        #pragma unroll
        for (int i = 0; i < 4; i++) {
            cp16(As + s*TSZ32 + dBase + i*1024, gA + (size_t)i*32*lda + ko);
            cp16(Bs + s*TSZ32 + dBase + i*1024, gB + (size_t)i*32*ldb + ko);
        }
        cp_commit();
    }
    cp_wait1();
    __syncthreads();

    for (int kt = 0; kt < KT; kt++) {
        const int cur = kt % 3;
        if (kt + 2 < KT) {
            const int st = (kt + 2) % 3;
            const size_t ko = (size_t)(kt + 2) * 32;
            #pragma unroll
            for (int i = 0; i < 4; i++) {
                cp16(As + st*TSZ32 + dBase + i*1024, gA + (size_t)i*32*lda + ko);
                cp16(Bs + st*TSZ32 + dBase + i*1024, gB + (size_t)i*32*ldb + ko);
            }
        }
        cp_commit();

        const unsigned aOff  = aBase  + (unsigned)cur * STB;
        const unsigned bOff0 = bBase0 + (unsigned)cur * STB;
        const unsigned bOff1 = bBase1 + (unsigned)cur * STB;

        #pragma unroll
        for (int ks = 0; ks < 4; ks++) {
            unsigned af[4][4];
            unsigned bf[4][2];
            #pragma unroll
            for (int i = 0; i < 4; i++)
                ldsm4(af[i][0], af[i][1], af[i][2], af[i][3],
                      aOff + (unsigned)i*2048 + tks[ks]);
            ldsm4(bf[0][0], bf[1][0], bf[0][1], bf[1][1], bOff0 + tks[ks]);
            ldsm4(bf[2][0], bf[3][0], bf[2][1], bf[3][1], bOff1 + tks[ks]);

            #pragma unroll
            for (int i = 0; i < 4; i++)
                #pragma unroll
                for (int j = 0; j < 4; j++) {
                    asm volatile(
                        "mma.sync.aligned.m16n8k8.row.col.f32.tf32.tf32.f32 "
                        "{%0,%1,%2,%3}, {%4,%5,%6,%7}, {%8,%9}, {%0,%1,%2,%3};"
                        : "+f"(acc[i][j][0]), "+f"(acc[i][j][1]),
                          "+f"(acc[i][j][2]), "+f"(acc[i][j][3])
                        : "r"(af[i][0]), "r"(af[i][1]), "r"(af[i][2]), "r"(af[i][3]),
                          "r"(bf[j][0]), "r"(bf[j][1]));
                }
        }

        cp_wait1();
        __syncthreads();
    }

    #pragma unroll
    for (int i = 0; i < 4; i++) {
        const int r0e = bm + wm + i*16 + u;
        #pragma unroll
        for (int j = 0; j < 4; j++) {
            const int c0 = bn + wn + j*8 + li*2;
            float v0 = acc[i][j][0], v1 = acc[i][j][1];
            float v2 = acc[i][j][2], v3 = acc[i][j][3];
            if (EPI == 1) {
                const float bA = bias[c0], bB = bias[c0+1];
                v0 += bA; v1 += bB; v2 += bA; v3 += bB;
                v0 = (v0 > 20.0f) ? v0 : log1pf(__expf(v0));
                v1 = (v1 > 20.0f) ? v1 : log1pf(__expf(v1));
                v2 = (v2 > 20.0f) ? v2 : log1pf(__expf(v2));
                v3 = (v3 > 20.0f) ? v3 : log1pf(__expf(v3));
            }
            *(float2*)&C[(size_t)r0e * ldc + c0]     = make_float2(v0, v1);
            *(float2*)&C[(size_t)(r0e+8) * ldc + c0] = make_float2(v2, v3);
        }
    }
}

// ---------------- fp32 tiled SGEMM, split-K (B/C part of x_proj: N=32) ----------------
// grid (KS, M/64): blockIdx.x = k-split; writes partial to C + split*M*ldc.
template<int BM, int BN, int BK, int TM, int TN>
__global__ __launch_bounds__(256)
void sgemm_splitk_kernel(int M, int N, int KC,     // KC = chunk length
                         const float* __restrict__ A, int lda,
                         const float* __restrict__ Bw, int ldb,
                         float* __restrict__ C, int ldc)
{
    __shared__ float As[BK][BM];
    __shared__ float Bs[BK][BN];

    const int tid = threadIdx.x;
    const int tx  = tid & 15;
    const int ty  = tid >> 4;
    const int bm  = blockIdx.y * BM;
    const int sk  = blockIdx.x;
    const size_t k0base = (size_t)sk * KC;
    C += (size_t)sk * M * ldc;

    float acc[TM][TN];
    #pragma unroll
    for (int i = 0; i < TM; i++)
        #pragma unroll
        for (int j = 0; j < TN; j++) acc[i][j] = 0.0f;

    const int a_m = tid / (BK/4);
    const int a_k = (tid % (BK/4)) * 4;

    for (int k0 = 0; k0 < KC; k0 += BK) {
        if (tid < (BM*BK/4)) {
            float4 v = *(const float4*)&A[(size_t)(bm + a_m)*lda + k0base + k0 + a_k];
            As[a_k+0][a_m] = v.x; As[a_k+1][a_m] = v.y;
            As[a_k+2][a_m] = v.z; As[a_k+3][a_m] = v.w;
        }
        if (tid < (BN*BK/4)) {
            float4 v = *(const float4*)&Bw[(size_t)a_m*ldb + k0base + k0 + a_k];
            Bs[a_k+0][a_m] = v.x; Bs[a_k+1][a_m] = v.y;
            Bs[a_k+2][a_m] = v.z; Bs[a_k+3][a_m] = v.w;
        }
        __syncthreads();

        #pragma unroll
        for (int k = 0; k < BK; k++) {
            float rm[TM], rn[TN];
            #pragma unroll
            for (int i = 0; i < TM; i++) rm[i] = As[k][ty*TM + i];
            #pragma unroll
            for (int j = 0; j < TN; j++) rn[j] = Bs[k][tx*TN + j];
            #pragma unroll
            for (int i = 0; i < TM; i++)
                #pragma unroll
                for (int j = 0; j < TN; j++)
                    acc[i][j] += rm[i] * rn[j];
        }
        __syncthreads();
    }

    #pragma unroll
    for (int i = 0; i < TM; i++) {
        const int m = bm + ty*TM + i;
        #pragma unroll
        for (int j = 0; j < TN; j++) {
            const int n = tx*TN + j;
            C[(size_t)m*ldc + n] = acc[i][j];
        }
    }
}

// ---------------- depthwise causal conv(k=4) + bias + silu, L-chunked ----------------
#define CLC 128
__global__ __launch_bounds__(256)
void conv_silu_kernel(const float* __restrict__ xz,
                      const float* __restrict__ w,
                      const float* __restrict__ bias,
                      float* __restrict__ xc,
                      float* __restrict__ xcr)
{
    const int d  = blockIdx.x * blockDim.x + threadIdx.x;
    const int b  = blockIdx.z;
    const int l0 = blockIdx.y * CLC;

    const float w0 = w[d*4+0], w1 = w[d*4+1], w2 = w[d*4+2], w3 = w[d*4+3];
    const float bi = bias[d];
    const float* px = xz  + ((size_t)b * L_ + l0) * EI + d;
    float*       po = xc  + ((size_t)b * L_ + l0) * DI + d;
    float*       pr = xcr + ((size_t)b * L_ + l0) * DI + d;

    float x0 = 0.f, x1 = 0.f, x2 = 0.f;
    if (l0 > 0) {
        x0 = px[-(size_t)3 * EI];
        x1 = px[-(size_t)2 * EI];
        x2 = px[-(size_t)1 * EI];
    }
    #pragma unroll 4
    for (int l = 0; l < CLC; l++) {
        float x3 = px[(size_t)l * EI];
        float v  = w0*x0 + w1*x1 + w2*x2 + w3*x3 + bi;
        v = v / (1.0f + __expf(-v));
        po[(size_t)l * DI] = v;
        pr[(size_t)l * DI] = tf32r(v);
        x0 = x1; x1 = x2; x2 = x3;
    }
}

// ---------------- selective scan: barrier-free, BC via shfl, prefetch 2 ----------------
__global__ __launch_bounds__(64)
void scan_kernel(const float* __restrict__ xz,
                 const float* __restrict__ xc,
                 const float* __restrict__ dt,
                 const float* __restrict__ bc,
                 const float* __restrict__ A_log,
                 const float* __restrict__ Dp,
                 float* __restrict__ y)
{
    const int b    = blockIdx.y;
    const int d    = blockIdx.x * 64 + threadIdx.x;
    const int lane = threadIdx.x & 31;

    float negA[DS];
    #pragma unroll
    for (int n = 0; n < DS; n++) negA[n] = -__expf(A_log[d*DS + n]);

    bool chain = (negA[0] != 0.0f);
    #pragma unroll
    for (int n = 1; n < DS; n++) {
        float r = negA[n] - (float)(n+1) * negA[0];
        if (fabsf(r) > 1e-4f * fabsf(negA[n])) chain = false;
    }

    const float Dd = Dp[d];
    float h[DS];
    #pragma unroll
    for (int n = 0; n < DS; n++) h[n] = 0.0f;

    const size_t rb = (size_t)b * L_;
    const float* pdt = dt + rb * DI + d;
    const float* pxc = xc + rb * DI + d;
    const float* pz  = xz + rb * EI + DI + d;
    const float* pbc = bc + rb * 32;
    float*       py  = y  + rb * DI + d;

    float bc0 = pbc[lane];
    float bc1 = pbc[32 + lane];
    float dt0 = pdt[0],  x0v = pxc[0],  z0v = pz[0];
    float dt1 = pdt[DI], x1v = pxc[DI], z1v = pz[EI];

    for (int l = 0; l < L_; l++) {
        float bc2 = 0.f, dt2 = 0.f, x2v = 0.f, z2v = 0.f;
        if (l + 2 < L_) {
            bc2 = pbc[(size_t)(l+2) * 32 + lane];
            dt2 = pdt[(size_t)(l+2) * DI];
            x2v = pxc[(size_t)(l+2) * DI];
            z2v = pz [(size_t)(l+2) * EI];
        }

        const float dtv = dt0;
        float dA[DS];
        if (chain) {
            float base = __expf(dtv * negA[0]);
            dA[0] = base;
            dA[1] = base * base;
            #pragma unroll
            for (int n = 2; n < DS; n++)
                dA[n] = dA[(n-1) >> 1] * dA[n >> 1];
        } else {
            #pragma unroll
            for (int n = 0; n < DS; n++) dA[n] = __expf(dtv * negA[n]);
        }

        const float du = dtv * x0v;
        float yv = 0.0f;
        #pragma unroll
        for (int n = 0; n < DS; n++) {
            const float Bn = __shfl_sync(0xFFFFFFFFu, bc0, n);
            const float Cn = __shfl_sync(0xFFFFFFFFu, bc0, 16 + n);
            h[n] = h[n] * dA[n] + du * Bn;
            yv  += h[n] * Cn;
        }
        yv += x0v * Dd;
        const float zs = z0v / (1.0f + __expf(-z0v));
        py[(size_t)l * DI] = tf32r(yv * zs);

        bc0 = bc1; dt0 = dt1; x0v = x1v; z0v = z1v;
        bc1 = bc2; dt1 = dt2; x1v = x2v; z1v = z2v;
    }
}

// ---------------- launch ----------------
extern "C" void kernel_launch(void* const* d_in, const int* in_sizes, int n_in,
                              void* d_out, int out_size)
{
    const float* hs    = (const float*)d_in[0];
    const float* w_in  = (const float*)d_in[1];
    const float* convw = (const float*)d_in[2];
    const float* convb = (const float*)d_in[3];
    const float* xpw   = (const float*)d_in[4];
    const float* dtw   = (const float*)d_in[5];
    const float* dtb   = (const float*)d_in[6];
    const float* outw  = (const float*)d_in[7];
    const float* Alog  = (const float*)d_in[8];
    const float* Dp    = (const float*)d_in[9];
    float*       out   = (float*)d_out;

    float *xz, *xc, *xcr, *bc, *bcp, *dtb_, *yb;
    float *hsc, *winc, *dtwc, *outwc, *xpwc, *dtlo, *dtlp;
    cudaGetSymbolAddress((void**)&xz,    g_xz);
    cudaGetSymbolAddress((void**)&xc,    g_xc);
    cudaGetSymbolAddress((void**)&xcr,   g_xcr);
    cudaGetSymbolAddress((void**)&bc,    g_bc);
    cudaGetSymbolAddress((void**)&bcp,   g_bcp);
    cudaGetSymbolAddress((void**)&dtb_,  g_dt);
    cudaGetSymbolAddress((void**)&yb,    g_y);
    cudaGetSymbolAddress((void**)&hsc,   g_hsc);
    cudaGetSymbolAddress((void**)&winc,  g_winc);
    cudaGetSymbolAddress((void**)&dtwc,  g_dtwc);
    cudaGetSymbolAddress((void**)&outwc, g_outwc);
    cudaGetSymbolAddress((void**)&xpwc,  g_xpwc);
    cudaGetSymbolAddress((void**)&dtlo,  g_dtlo);
    cudaGetSymbolAddress((void**)&dtlp,  g_dtlp);

    const dim3 t256(256);
    const size_t msmem = 6 * TSZ32 * sizeof(float);
    const size_t wsmem = 4 * (TSZ_A + TSZ_B) * sizeof(float);

    cudaFuncSetAttribute((const void*)&mma_gemm<1,0>, cudaFuncAttributeMaxDynamicSharedMemorySize, (int)msmem);
    cudaFuncSetAttribute((const void*)&mma_gemm<0,1>, cudaFuncAttributeMaxDynamicSharedMemorySize, (int)msmem);
    cudaFuncSetAttribute((const void*)&mma_gemm_wide, cudaFuncAttributeMaxDynamicSharedMemorySize, (int)wsmem);

    // 0) fused tf32 pre-rounding
    {
        const size_t n0 = (size_t)ML*DM/4, n1 = (size_t)EI*DM/4,
                     n2 = (size_t)DI*DTR/4, n3 = (size_t)DM*DI/4,
                     n4 = (size_t)DTR*DI/4;
        const size_t nt = n0 + n1 + n2 + n3 + n4;
        round_all_kernel<<<(unsigned)((nt+255)/256), t256>>>(
            hs, hsc, n0, w_in, winc, n1, dtw, dtwc, n2, outw, outwc, n3, xpw, xpwc, n4);
    }

    // 1) in_proj (wide tf32 mma)
    mma_gemm_wide<<<dim3(EI/256, ML/128), dim3(512), wsmem>>>(
        ML, EI, DM, hsc, DM, winc, DM, xz, EI);

    // 2) depthwise conv + silu
    conv_silu_kernel<<<dim3(DI/256, L_/CLC, B_), t256>>>(xz, convw, convb, xc, xcr);

    // 3a) x_proj B/C (fp32 split-K x8)
    sgemm_splitk_kernel<64,32,16,4,2><<<dim3(KS_BC, ML/64), t256>>>(
        ML, 32, DI/KS_BC, xc, DI, xpw + (size_t)DTR*DI, DI, bcp, 32);

    // 3b) x_proj dt_lo (tf32 mma split-K x4)
    mma_gemm<0,1><<<dim3(KS_DT, ML/128), t256, msmem>>>(
        ML, DTR, DI/KS_DT, xcr, DI, xpwc, DI, dtlp, DTR, nullptr);

    // 3c) reduce split-K partials (bc exact, dtlo tf32-rounded)
    {
        const size_t nt = (size_t)ML*32/4 + (size_t)ML*DTR/4;
        reduce_splitk_kernel<<<(unsigned)((nt+255)/256), t256>>>(bcp, bc, dtlp, dtlo);
    }

    // 4) dt_proj + softplus (tf32 mma)
    mma_gemm<1,0><<<dim3(DI/128, ML/128), t256, msmem>>>(
        ML, DI, DTR, dtlo, DTR, dtwc, DTR, dtb_, DI, dtb);

    // 5) selective scan
    scan_kernel<<<dim3(DI/64, B_), dim3(64)>>>(
        xz, xc, dtb_, bc, Alog, Dp, yb);

    // 6) out_proj (wide tf32 mma)
    mma_gemm_wide<<<dim3(DM/256, ML/128), dim3(512), wsmem>>>(
        ML, DM, DI, yb, DI, outwc, DI, out, DM);
}

// round 11
// speedup vs baseline: 1.6806x; 1.0073x over previous
#include <cuda_runtime.h>
#include <cstdint>
#include <cstddef>

// ---------------- problem constants ----------------
#define B_   2
#define L_   2048
#define DM   2048          // d_model
#define DI   4096          // d_inner
#define EI   8192          // 2*d_inner
#define DS   16            // d_state
#define DTR  128           // dt_rank
#define XD   160           // dt_rank + 2*d_state
#define ML   (B_*L_)       // 4096 rows

#define KS_BC 8            // split-K for B/C sgemm
#define KS_DT 4            // split-K for dt_lo mma

// ---------------- scratch (device globals; no allocation allowed) ----------------
__device__ float g_xz  [(size_t)ML * EI];
__device__ float g_xc  [(size_t)ML * DI];   // conv+silu (exact fp32)
__device__ float g_xcr [(size_t)ML * DI];   // conv+silu (tf32-rounded)
__device__ float g_bc  [(size_t)ML * 32];   // B(16) + C(16) per row, fp32
__device__ float g_bcp [(size_t)KS_BC * ML * 32];   // split-K partials
__device__ float g_dt  [(size_t)ML * DI];
__device__ float g_y   [(size_t)ML * DI];   // scan output (tf32-rounded)
__device__ float g_hsc [(size_t)ML * DM];   // tf32-rounded hidden_states
__device__ float g_winc[(size_t)EI * DM];   // tf32-rounded in_proj_weight
__device__ float g_dtwc[(size_t)DI * DTR];  // tf32-rounded dt_proj_weight
__device__ float g_outwc[(size_t)DM * DI];  // tf32-rounded out_proj_weight
__device__ float g_xpwc[(size_t)DTR * DI];  // tf32-rounded x_proj_weight rows 0..127
__device__ float g_dtlo[(size_t)ML * DTR];  // tf32 dt_lo (compact)
__device__ float g_dtlp[(size_t)KS_DT * ML * DTR];  // split-K partials

__device__ __forceinline__ unsigned f2tf32(float f) {
    unsigned u;
    asm("cvt.rna.tf32.f32 %0, %1;" : "=r"(u) : "f"(f));
    return u;
}
__device__ __forceinline__ float tf32r(float f) {
    return __uint_as_float(f2tf32(f));
}

// ---------------- fused tf32 rounding: 5 segments in one launch ----------------
__global__ __launch_bounds__(256)
void round_all_kernel(const float* s0, float* d0, size_t n0,
                      const float* s1, float* d1, size_t n1,
                      const float* s2, float* d2, size_t n2,
                      const float* s3, float* d3, size_t n3,
                      const float* s4, float* d4, size_t n4)
{
    size_t i = (size_t)blockIdx.x * blockDim.x + threadIdx.x;
    const float* s; float* d;
    if (i < n0) { s = s0; d = d0; }
    else if ((i -= n0) < n1) { s = s1; d = d1; }
    else if ((i -= n1) < n2) { s = s2; d = d2; }
    else if ((i -= n2) < n3) { s = s3; d = d3; }
    else if ((i -= n3) < n4) { s = s4; d = d4; }
    else return;
    float4 v = ((const float4*)s)[i];
    v.x = tf32r(v.x); v.y = tf32r(v.y); v.z = tf32r(v.z); v.w = tf32r(v.w);
    ((float4*)d)[i] = v;
}

// ---------------- split-K reduce: bc (8 partials) + dtlo (4 partials, tf32r) ----------------
__global__ __launch_bounds__(256)
void reduce_splitk_kernel(const float* __restrict__ bcp, float* __restrict__ bc,
                          const float* __restrict__ dtlp, float* __restrict__ dtlo)
{
    const size_t nBC = (size_t)ML * 32 / 4;
    const size_t nDT = (size_t)ML * DTR / 4;
    size_t i = (size_t)blockIdx.x * blockDim.x + threadIdx.x;
    if (i < nBC) {
        float4 a = ((const float4*)bcp)[i];
        #pragma unroll
        for (int s = 1; s < KS_BC; s++) {
            float4 p = ((const float4*)(bcp + (size_t)s * ML * 32))[i];
            a.x += p.x; a.y += p.y; a.z += p.z; a.w += p.w;
        }
        ((float4*)bc)[i] = a;
    } else if ((i -= nBC) < nDT) {
        float4 a = ((const float4*)dtlp)[i];
        #pragma unroll
        for (int s = 1; s < KS_DT; s++) {
            float4 p = ((const float4*)(dtlp + (size_t)s * ML * DTR))[i];
            a.x += p.x; a.y += p.y; a.z += p.z; a.w += p.w;
        }
        a.x = tf32r(a.x); a.y = tf32r(a.y); a.z = tf32r(a.z); a.w = tf32r(a.w);
        ((float4*)dtlo)[i] = a;
    }
}

// ---------------- async-copy + ldmatrix helpers ----------------
__device__ __forceinline__ void cp16(float* smem_dst, const float* gmem_src) {
    unsigned s = (unsigned)__cvta_generic_to_shared(smem_dst);
    asm volatile("cp.async.cg.shared.global [%0], [%1], 16;\n" :: "r"(s), "l"(gmem_src));
}
__device__ __forceinline__ void cp_commit() {
    asm volatile("cp.async.commit_group;\n");
}
__device__ __forceinline__ void cp_wait1() {
    asm volatile("cp.async.wait_group 1;\n");
}
__device__ __forceinline__ void cp_wait2() {
    asm volatile("cp.async.wait_group 2;\n");
}
__device__ __forceinline__ void ldsm4(unsigned& r0, unsigned& r1, unsigned& r2, unsigned& r3,
                                      unsigned addr) {
    asm volatile("ldmatrix.sync.aligned.m8n8.x4.shared.b16 {%0,%1,%2,%3}, [%4];"
                 : "=r"(r0), "=r"(r1), "=r"(r2), "=r"(r3) : "r"(addr));
}

// =========================================================================
// WIDE TF32 GEMM: BM=128, BN=256, BK=32, 512 threads (16 warps, 2m x 8n),
// warp tile 64x32, 4-stage cp.async (wait_group 2), ldmatrix fragments.
// =========================================================================
#define TSZ_A 4096
#define TSZ_B 8192
#define STB_A 16384u
#define STB_B 32768u

__global__ __launch_bounds__(512, 1)
void mma_gemm_wide(int M, int N, int K,
                   const float* __restrict__ A, int lda,
                   const float* __restrict__ Bw, int ldb,
                   float* __restrict__ C, int ldc)
{
    extern __shared__ float smem[];
    float* As = smem;
    float* Bs = smem + 4*TSZ_A;

    const int tid  = threadIdx.x;
    const int lane = tid & 31;
    const int warp = tid >> 5;
    const int wm   = (warp & 1) * 64;
    const int wn   = (warp >> 1) * 32;
    const int bm   = blockIdx.y * 128;
    const int bn   = blockIdx.x * 256;

    const int q     = tid & 7;
    const int r0    = tid >> 3;
    const int pq    = q ^ (r0 & 7);
    const int dBase = r0*32 + pq*4;

    const float* gA = A  + (size_t)(bm + r0) * lda + q*4;
    const float* gB = Bw + (size_t)(bn + r0) * ldb + q*4;

    const int g    = lane >> 3;
    const int kg   = g >> 1;
    const int sub8 = (g & 1) << 3;
    const int lr   = lane & 7;
    const unsigned aSh = (unsigned)__cvta_generic_to_shared(As);
    const unsigned bSh = (unsigned)__cvta_generic_to_shared(Bs);
    const unsigned aBase  = aSh + (unsigned)(wm + sub8 + lr) * 128;
    const unsigned bBase0 = bSh + (unsigned)(wn + sub8 + lr) * 128;
    const unsigned bBase1 = bBase0 + 16*128;
    unsigned tks[4];
    #pragma unroll
    for (int ks = 0; ks < 4; ks++)
        tks[ks] = (unsigned)(((((ks << 1) + kg) ^ lr) & 7) << 4);

    const int u  = lane >> 2;
    const int li = lane & 3;

    float acc[4][4][4];
    #pragma unroll
    for (int i = 0; i < 4; i++)
        #pragma unroll
        for (int j = 0; j < 4; j++)
            #pragma unroll
            for (int r = 0; r < 4; r++) acc[i][j][r] = 0.0f;

    const int KT = K / 32;

    #pragma unroll
    for (int s = 0; s < 2; s++) {
        const size_t ko = (size_t)s * 32;
        #pragma unroll
        for (int i = 0; i < 2; i++)
            cp16(As + s*TSZ_A + dBase + i*2048, gA + (size_t)i*64*lda + ko);
        #pragma unroll
        for (int i = 0; i < 4; i++)
            cp16(Bs + s*TSZ_B + dBase + i*2048, gB + (size_t)i*64*ldb + ko);
        cp_commit();
    }

    for (int kt = 0; kt < KT; kt++) {
        const int cur = kt & 3;
        if (kt + 2 < KT) {
            const int st = (kt + 2) & 3;
            const size_t ko = (size_t)(kt + 2) * 32;
            #pragma unroll
            for (int i = 0; i < 2; i++)
                cp16(As + st*TSZ_A + dBase + i*2048, gA + (size_t)i*64*lda + ko);
            #pragma unroll
            for (int i = 0; i < 4; i++)
                cp16(Bs + st*TSZ_B + dBase + i*2048, gB + (size_t)i*64*ldb + ko);
        }
        cp_commit();
        cp_wait2();
        __syncthreads();

        const unsigned aOff  = aBase  + (unsigned)cur * STB_A;
        const unsigned bOff0 = bBase0 + (unsigned)cur * STB_B;
        const unsigned bOff1 = bBase1 + (unsigned)cur * STB_B;

        #pragma unroll
        for (int ks = 0; ks < 4; ks++) {
            unsigned af[4][4];
            unsigned bf[4][2];
            #pragma unroll
            for (int i = 0; i < 4; i++)
                ldsm4(af[i][0], af[i][1], af[i][2], af[i][3],
                      aOff + (unsigned)i*2048 + tks[ks]);
            ldsm4(bf[0][0], bf[1][0], bf[0][1], bf[1][1], bOff0 + tks[ks]);
            ldsm4(bf[2][0], bf[3][0], bf[2][1], bf[3][1], bOff1 + tks[ks]);

            #pragma unroll
            for (int i = 0; i < 4; i++)
                #pragma unroll
                for (int j = 0; j < 4; j++) {
                    asm volatile(
                        "mma.sync.aligned.m16n8k8.row.col.f32.tf32.tf32.f32 "
                        "{%0,%1,%2,%3}, {%4,%5,%6,%7}, {%8,%9}, {%0,%1,%2,%3};"
                        : "+f"(acc[i][j][0]), "+f"(acc[i][j][1]),
                          "+f"(acc[i][j][2]), "+f"(acc[i][j][3])
                        : "r"(af[i][0]), "r"(af[i][1]), "r"(af[i][2]), "r"(af[i][3]),
                          "r"(bf[j][0]), "r"(bf[j][1]));
                }
        }
    }

    #pragma unroll
    for (int i = 0; i < 4; i++) {
        const int r0e = bm + wm + i*16 + u;
        #pragma unroll
        for (int j = 0; j < 4; j++) {
            const int c0 = bn + wn + j*8 + li*2;
            *(float2*)&C[(size_t)r0e * ldc + c0]     = make_float2(acc[i][j][0], acc[i][j][1]);
            *(float2*)&C[(size_t)(r0e+8) * ldc + c0] = make_float2(acc[i][j][2], acc[i][j][3]);
        }
    }
}

// ================= mma.sync TF32 GEMM BN=128 =================
// EPI: 0 = none, 1 = softplus(v+bias[n])
// SPLITK: blockIdx.x = k-split index (N must be 128); partial -> C + split*M*ldc
#define TSZ32 4096
#define STB   16384u

template<int EPI, int SPLITK>
__global__ __launch_bounds__(256, 2)
void mma_gemm(int M, int N, int K,
              const float* __restrict__ A, int lda,
              const float* __restrict__ Bw, int ldb,
              float* __restrict__ C, int ldc,
              const float* __restrict__ bias)
{
    extern __shared__ float smem[];
    float* As = smem;
    float* Bs = smem + 3*TSZ32;

    const int tid  = threadIdx.x;
    const int lane = tid & 31;
    const int warp = tid >> 5;
    const int wm   = (warp & 1) * 64;
    const int wn   = (warp >> 1) * 32;
    const int bm   = blockIdx.y * 128;
    int bn = 0;
    if (SPLITK) {
        const int sk = blockIdx.x;
        A  += (size_t)sk * K;
        Bw += (size_t)sk * K;
        C  += (size_t)sk * M * ldc;
    } else {
        bn = blockIdx.x * 128;
    }

    const int q     = tid & 7;
    const int r0    = tid >> 3;
    const int pq    = q ^ (r0 & 7);
    const int dBase = r0*32 + pq*4;

    const float* gA = A  + (size_t)(bm + r0) * lda + q*4;
    const float* gB = Bw + (size_t)(bn + r0) * ldb + q*4;

    const int g    = lane >> 3;
    const int kg   = g >> 1;
    const int sub8 = (g & 1) << 3;
    const int lr   = lane & 7;
    const unsigned aSh = (unsigned)__cvta_generic_to_shared(As);
    const unsigned bSh = (unsigned)__cvta_generic_to_shared(Bs);
    const unsigned aBase  = aSh + (unsigned)(wm + sub8 + lr) * 128;
    const unsigned bBase0 = bSh + (unsigned)(wn + sub8 + lr) * 128;
    const unsigned bBase1 = bBase0 + 16*128;
    unsigned tks[4];
    #pragma unroll
    for (int ks = 0; ks < 4; ks++)
        tks[ks] = (unsigned)(((((ks << 1) + kg) ^ lr) & 7) << 4);

    const int u  = lane >> 2;
    const int li = lane & 3;

    float acc[4][4][4];
    #pragma unroll
    for (int i = 0; i < 4; i++)
        #pragma unroll
        for (int j = 0; j < 4; j++)
            #pragma unroll
            for (int r = 0; r < 4; r++) acc[i][j][r] = 0.0f;

    const int KT = K / 32;

    #pragma unroll
    for (int s = 0; s < 2; s++) {
        const size_t ko = (size_t)s * 32;
        #pragma unroll
        for (int i = 0; i < 4; i++) {
            cp16(As + s*TSZ32 + dBase + i*1024, gA + (size_t)i*32*lda + ko);
            cp16(Bs + s*TSZ32 + dBase + i*1024, gB + (size_t)i*32*ldb + ko);
        }
        cp_commit();
    }
    cp_wait1();
    __syncthreads();

    for (int kt = 0; kt < KT; kt++) {
        const int cur = kt % 3;
        if (kt + 2 < KT) {
            const int st = (kt + 2) % 3;
            const size_t ko = (size_t)(kt + 2) * 32;
            #pragma unroll
            for (int i = 0; i < 4; i++) {
                cp16(As + st*TSZ32 + dBase + i*1024, gA + (size_t)i*32*lda + ko);
                cp16(Bs + st*TSZ32 + dBase + i*1024, gB + (size_t)i*32*ldb + ko);
            }
        }
        cp_commit();

        const unsigned aOff  = aBase  + (unsigned)cur * STB;
        const unsigned bOff0 = bBase0 + (unsigned)cur * STB;
        const unsigned bOff1 = bBase1 + (unsigned)cur * STB;

        #pragma unroll
        for (int ks = 0; ks < 4; ks++) {
            unsigned af[4][4];
            unsigned bf[4][2];
            #pragma unroll
            for (int i = 0; i < 4; i++)
                ldsm4(af[i][0], af[i][1], af[i][2], af[i][3],
                      aOff + (unsigned)i*2048 + tks[ks]);
            ldsm4(bf[0][0], bf[1][0], bf[0][1], bf[1][1], bOff0 + tks[ks]);
            ldsm4(bf[2][0], bf[3][0], bf[2][1], bf[3][1], bOff1 + tks[ks]);

            #pragma unroll
            for (int i = 0; i < 4; i++)
                #pragma unroll
                for (int j = 0; j < 4; j++) {
                    asm volatile(
                        "mma.sync.aligned.m16n8k8.row.col.f32.tf32.tf32.f32 "
                        "{%0,%1,%2,%3}, {%4,%5,%6,%7}, {%8,%9}, {%0,%1,%2,%3};"
                        : "+f"(acc[i][j][0]), "+f"(acc[i][j][1]),
                          "+f"(acc[i][j][2]), "+f"(acc[i][j][3])
                        : "r"(af[i][0]), "r"(af[i][1]), "r"(af[i][2]), "r"(af[i][3]),
                          "r"(bf[j][0]), "r"(bf[j][1]));
                }
        }

        cp_wait1();
        __syncthreads();
    }

    #pragma unroll
    for (int i = 0; i < 4; i++) {
        const int r0e = bm + wm + i*16 + u;
        #pragma unroll
        for (int j = 0; j < 4; j++) {
            const int c0 = bn + wn + j*8 + li*2;
            float v0 = acc[i][j][0], v1 = acc[i][j][1];
            float v2 = acc[i][j][2], v3 = acc[i][j][3];
            if (EPI == 1) {
                const float bA = bias[c0], bB = bias[c0+1];
                v0 += bA; v1 += bB; v2 += bA; v3 += bB;
                v0 = (v0 > 20.0f) ? v0 : log1pf(__expf(v0));
                v1 = (v1 > 20.0f) ? v1 : log1pf(__expf(v1));
                v2 = (v2 > 20.0f) ? v2 : log1pf(__expf(v2));
                v3 = (v3 > 20.0f) ? v3 : log1pf(__expf(v3));
            }
            *(float2*)&C[(size_t)r0e * ldc + c0]     = make_float2(v0, v1);
            *(float2*)&C[(size_t)(r0e+8) * ldc + c0] = make_float2(v2, v3);
        }
    }
}

// ---------------- fp32 tiled SGEMM, split-K (B/C part of x_proj: N=32) ----------------
template<int BM, int BN, int BK, int TM, int TN>
__global__ __launch_bounds__(256)
void sgemm_splitk_kernel(int M, int N, int KC,
                         const float* __restrict__ A, int lda,
                         const float* __restrict__ Bw, int ldb,
                         float* __restrict__ C, int ldc)
{
    __shared__ float As[BK][BM];
    __shared__ float Bs[BK][BN];

    const int tid = threadIdx.x;
    const int tx  = tid & 15;
    const int ty  = tid >> 4;
    const int bm  = blockIdx.y * BM;
    const int sk  = blockIdx.x;
    const size_t k0base = (size_t)sk * KC;
    C += (size_t)sk * M * ldc;

    float acc[TM][TN];
    #pragma unroll
    for (int i = 0; i < TM; i++)
        #pragma unroll
        for (int j = 0; j < TN; j++) acc[i][j] = 0.0f;

    const int a_m = tid / (BK/4);
    const int a_k = (tid % (BK/4)) * 4;

    for (int k0 = 0; k0 < KC; k0 += BK) {
        if (tid < (BM*BK/4)) {
            float4 v = *(const float4*)&A[(size_t)(bm + a_m)*lda + k0base + k0 + a_k];
            As[a_k+0][a_m] = v.x; As[a_k+1][a_m] = v.y;
            As[a_k+2][a_m] = v.z; As[a_k+3][a_m] = v.w;
        }
        if (tid < (BN*BK/4)) {
            float4 v = *(const float4*)&Bw[(size_t)a_m*ldb + k0base + k0 + a_k];
            Bs[a_k+0][a_m] = v.x; Bs[a_k+1][a_m] = v.y;
            Bs[a_k+2][a_m] = v.z; Bs[a_k+3][a_m] = v.w;
        }
        __syncthreads();

        #pragma unroll
        for (int k = 0; k < BK; k++) {
            float rm[TM], rn[TN];
            #pragma unroll
            for (int i = 0; i < TM; i++) rm[i] = As[k][ty*TM + i];
            #pragma unroll
            for (int j = 0; j < TN; j++) rn[j] = Bs[k][tx*TN + j];
            #pragma unroll
            for (int i = 0; i < TM; i++)
                #pragma unroll
                for (int j = 0; j < TN; j++)
                    acc[i][j] += rm[i] * rn[j];
        }
        __syncthreads();
    }

    #pragma unroll
    for (int i = 0; i < TM; i++) {
        const int m = bm + ty*TM + i;
        #pragma unroll
        for (int j = 0; j < TN; j++) {
            const int n = tx*TN + j;
            C[(size_t)m*ldc + n] = acc[i][j];
        }
    }
}

// ---------------- depthwise causal conv(k=4) + bias + silu, L-chunked ----------------
#define CLC 128
__global__ __launch_bounds__(256)
void conv_silu_kernel(const float* __restrict__ xz,
                      const float* __restrict__ w,
                      const float* __restrict__ bias,
                      float* __restrict__ xc,
                      float* __restrict__ xcr)
{
    const int d  = blockIdx.x * blockDim.x + threadIdx.x;
    const int b  = blockIdx.z;
    const int l0 = blockIdx.y * CLC;

    const float w0 = w[d*4+0], w1 = w[d*4+1], w2 = w[d*4+2], w3 = w[d*4+3];
    const float bi = bias[d];
    const float* px = xz  + ((size_t)b * L_ + l0) * EI + d;
    float*       po = xc  + ((size_t)b * L_ + l0) * DI + d;
    float*       pr = xcr + ((size_t)b * L_ + l0) * DI + d;

    float x0 = 0.f, x1 = 0.f, x2 = 0.f;
    if (l0 > 0) {
        x0 = px[-(size_t)3 * EI];
        x1 = px[-(size_t)2 * EI];
        x2 = px[-(size_t)1 * EI];
    }
    #pragma unroll 4
    for (int l = 0; l < CLC; l++) {
        float x3 = px[(size_t)l * EI];
        float v  = w0*x0 + w1*x1 + w2*x2 + w3*x3 + bi;
        v = v / (1.0f + __expf(-v));
        po[(size_t)l * DI] = v;
        pr[(size_t)l * DI] = tf32r(v);
        x0 = x1; x1 = x2; x2 = x3;
    }
}

// ---------------- selective scan: state-parallel (4 lanes per channel) ----------------
// warp = 8 channels x 4 state-lanes; 8 idx-shfl + 2 bfly-shfl per step.
__global__ __launch_bounds__(128)
void scan_kernel(const float* __restrict__ xz,
                 const float* __restrict__ xc,
                 const float* __restrict__ dt,
                 const float* __restrict__ bc,
                 const float* __restrict__ A_log,
                 const float* __restrict__ Dp,
                 float* __restrict__ y)
{
    const int b    = blockIdx.y;
    const int tid  = threadIdx.x;
    const int wid  = tid >> 5;
    const int lane = tid & 31;
    const int sub  = lane & 3;                       // state group 0..3
    const int d    = blockIdx.x * 32 + wid * 8 + (lane >> 2);

    // this lane owns states n = sub*4 + j, j=0..3
    float negA[4];
    #pragma unroll
    for (int j = 0; j < 4; j++)
        negA[j] = -__expf(A_log[d*DS + sub*4 + j]);
    const float negA0 = -__expf(A_log[d*DS]);

    // chain validity over ALL 16 states of this channel (one-time)
    bool chain = (negA0 != 0.0f);
    #pragma unroll
    for (int n = 1; n < DS; n++) {
        float na = -__expf(A_log[d*DS + n]);
        float r  = na - (float)(n+1) * negA0;
        if (fabsf(r) > 1e-4f * fabsf(na)) chain = false;
    }

    const float Dd = Dp[d];
    float h[4] = {0.f, 0.f, 0.f, 0.f};

    const size_t rb = (size_t)b * L_;
    const float* pdt = dt + rb * DI + d;
    const float* pxc = xc + rb * DI + d;
    const float* pz  = xz + rb * EI + DI + d;
    const float* pbc = bc + rb * 32;
    float*       py  = y  + rb * DI + d;

    // prefetch l = 0, 1
    float bc0 = pbc[lane];
    float bc1 = pbc[32 + lane];
    float dt0 = pdt[0],  x0v = pxc[0],  z0v = pz[0];
    float dt1 = pdt[DI], x1v = pxc[DI], z1v = pz[EI];

    for (int l = 0; l < L_; l++) {
        float bc2 = 0.f, dt2 = 0.f, x2v = 0.f, z2v = 0.f;
        if (l + 2 < L_) {
            bc2 = pbc[(size_t)(l+2) * 32 + lane];
            dt2 = pdt[(size_t)(l+2) * DI];
            x2v = pxc[(size_t)(l+2) * DI];
            z2v = pz [(size_t)(l+2) * EI];
        }

        const float dtv = dt0;
        float dA[4];
        if (chain) {
            const float b1 = __expf(dtv * negA0);
            const float b2 = b1*b1, b3 = b2*b1, b4 = b2*b2;
            const float b8 = b4*b4, b12 = b8*b4;
            const float pw = (sub == 0) ? 1.0f : (sub == 1) ? b4 : (sub == 2) ? b8 : b12;
            dA[0] = pw*b1; dA[1] = pw*b2; dA[2] = pw*b3; dA[3] = pw*b4;
        } else {
            #pragma unroll
            for (int j = 0; j < 4; j++) dA[j] = __expf(dtv * negA[j]);
        }

        const float du = dtv * x0v;
        float yp = 0.0f;
        #pragma unroll
        for (int j = 0; j < 4; j++) {
            const float Bn = __shfl_sync(0xFFFFFFFFu, bc0, sub*4 + j);
            const float Cn = __shfl_sync(0xFFFFFFFFu, bc0, 16 + sub*4 + j);
            h[j] = h[j] * dA[j] + du * Bn;
            yp  += h[j] * Cn;
        }
        // reduce across the 4 state-lanes of this channel
        yp += __shfl_xor_sync(0xFFFFFFFFu, yp, 1);
        yp += __shfl_xor_sync(0xFFFFFFFFu, yp, 2);

        if (sub == 0) {
            const float yv = yp + x0v * Dd;
            const float zs = z0v / (1.0f + __expf(-z0v));
            py[(size_t)l * DI] = tf32r(yv * zs);
        }

        bc0 = bc1; dt0 = dt1; x0v = x1v; z0v = z1v;
        bc1 = bc2; dt1 = dt2; x1v = x2v; z1v = z2v;
    }
}

// ---------------- launch ----------------
extern "C" void kernel_launch(void* const* d_in, const int* in_sizes, int n_in,
                              void* d_out, int out_size)
{
    const float* hs    = (const float*)d_in[0];
    const float* w_in  = (const float*)d_in[1];
    const float* convw = (const float*)d_in[2];
    const float* convb = (const float*)d_in[3];
    const float* xpw   = (const float*)d_in[4];
    const float* dtw   = (const float*)d_in[5];
    const float* dtb   = (const float*)d_in[6];
    const float* outw  = (const float*)d_in[7];
    const float* Alog  = (const float*)d_in[8];
    const float* Dp    = (const float*)d_in[9];
    float*       out   = (float*)d_out;

    float *xz, *xc, *xcr, *bc, *bcp, *dtb_, *yb;
    float *hsc, *winc, *dtwc, *outwc, *xpwc, *dtlo, *dtlp;
    cudaGetSymbolAddress((void**)&xz,    g_xz);
    cudaGetSymbolAddress((void**)&xc,    g_xc);
    cudaGetSymbolAddress((void**)&xcr,   g_xcr);
    cudaGetSymbolAddress((void**)&bc,    g_bc);
    cudaGetSymbolAddress((void**)&bcp,   g_bcp);
    cudaGetSymbolAddress((void**)&dtb_,  g_dt);
    cudaGetSymbolAddress((void**)&yb,    g_y);
    cudaGetSymbolAddress((void**)&hsc,   g_hsc);
    cudaGetSymbolAddress((void**)&winc,  g_winc);
    cudaGetSymbolAddress((void**)&dtwc,  g_dtwc);
    cudaGetSymbolAddress((void**)&outwc, g_outwc);
    cudaGetSymbolAddress((void**)&xpwc,  g_xpwc);
    cudaGetSymbolAddress((void**)&dtlo,  g_dtlo);
    cudaGetSymbolAddress((void**)&dtlp,  g_dtlp);

    const dim3 t256(256);
    const size_t msmem = 6 * TSZ32 * sizeof(float);
    const size_t wsmem = 4 * (TSZ_A + TSZ_B) * sizeof(float);

    cudaFuncSetAttribute((const void*)&mma_gemm<1,0>, cudaFuncAttributeMaxDynamicSharedMemorySize, (int)msmem);
    cudaFuncSetAttribute((const void*)&mma_gemm<0,1>, cudaFuncAttributeMaxDynamicSharedMemorySize, (int)msmem);
    cudaFuncSetAttribute((const void*)&mma_gemm_wide, cudaFuncAttributeMaxDynamicSharedMemorySize, (int)wsmem);

    // 0) fused tf32 pre-rounding
    {
        const size_t n0 = (size_t)ML*DM/4, n1 = (size_t)EI*DM/4,
                     n2 = (size_t)DI*DTR/4, n3 = (size_t)DM*DI/4,
                     n4 = (size_t)DTR*DI/4;
        const size_t nt = n0 + n1 + n2 + n3 + n4;
        round_all_kernel<<<(unsigned)((nt+255)/256), t256>>>(
            hs, hsc, n0, w_in, winc, n1, dtw, dtwc, n2, outw, outwc, n3, xpw, xpwc, n4);
    }

    // 1) in_proj (wide tf32 mma)
    mma_gemm_wide<<<dim3(EI/256, ML/128), dim3(512), wsmem>>>(
        ML, EI, DM, hsc, DM, winc, DM, xz, EI);

    // 2) depthwise conv + silu
    conv_silu_kernel<<<dim3(DI/256, L_/CLC, B_), t256>>>(xz, convw, convb, xc, xcr);

    // 3a) x_proj B/C (fp32 split-K x8)
    sgemm_splitk_kernel<64,32,16,4,2><<<dim3(KS_BC, ML/64), t256>>>(
        ML, 32, DI/KS_BC, xc, DI, xpw + (size_t)DTR*DI, DI, bcp, 32);

    // 3b) x_proj dt_lo (tf32 mma split-K x4)
    mma_gemm<0,1><<<dim3(KS_DT, ML/128), t256, msmem>>>(
        ML, DTR, DI/KS_DT, xcr, DI, xpwc, DI, dtlp, DTR, nullptr);

    // 3c) reduce split-K partials
    {
        const size_t nt = (size_t)ML*32/4 + (size_t)ML*DTR/4;
        reduce_splitk_kernel<<<(unsigned)((nt+255)/256), t256>>>(bcp, bc, dtlp, dtlo);
    }

    // 4) dt_proj + softplus (tf32 mma)
    mma_gemm<1,0><<<dim3(DI/128, ML/128), t256, msmem>>>(
        ML, DI, DTR, dtlo, DTR, dtwc, DTR, dtb_, DI, dtb);

    // 5) selective scan (state-parallel, 4 lanes/channel)
    scan_kernel<<<dim3(DI/32, B_), dim3(128)>>>(
        xz, xc, dtb_, bc, Alog, Dp, yb);

    // 6) out_proj (wide tf32 mma)
    mma_gemm_wide<<<dim3(DM/256, ML/128), dim3(512), wsmem>>>(
        ML, DM, DI, yb, DI, outwc, DI, out, DM);
}

// round 12
// speedup vs baseline: 2.0847x; 1.2405x over previous
#include <cuda_runtime.h>
#include <cstdint>
#include <cstddef>

// ---------------- problem constants ----------------
#define B_   2
#define L_   2048
#define DM   2048          // d_model
#define DI   4096          // d_inner
#define EI   8192          // 2*d_inner
#define DS   16            // d_state
#define DTR  128           // dt_rank
#define XD   160           // dt_rank + 2*d_state
#define ML   (B_*L_)       // 4096 rows

#define KS_BC 8            // split-K for B/C sgemm
#define KS_DT 4            // split-K for dt_lo mma

// ---------------- scratch (device globals; no allocation allowed) ----------------
__device__ float g_xz  [(size_t)ML * EI];
__device__ float g_xc  [(size_t)ML * DI];   // conv+silu (exact fp32)
__device__ float g_xcr [(size_t)ML * DI];   // conv+silu (tf32-rounded)
__device__ float g_bc  [(size_t)ML * 32];   // B(16) + C(16) per row, fp32
__device__ float g_bcp [(size_t)KS_BC * ML * 32];   // split-K partials
__device__ float g_dt  [(size_t)ML * DI];
__device__ float g_y   [(size_t)ML * DI];   // scan output (tf32-rounded)
__device__ float g_hsc [(size_t)ML * DM];   // tf32-rounded hidden_states
__device__ float g_winc[(size_t)EI * DM];   // tf32-rounded in_proj_weight
__device__ float g_dtwc[(size_t)DI * DTR];  // tf32-rounded dt_proj_weight
__device__ float g_outwc[(size_t)DM * DI];  // tf32-rounded out_proj_weight
__device__ float g_xpwc[(size_t)DTR * DI];  // tf32-rounded x_proj_weight rows 0..127
__device__ float g_dtlo[(size_t)ML * DTR];  // tf32 dt_lo (compact)
__device__ float g_dtlp[(size_t)KS_DT * ML * DTR];  // split-K partials

__device__ __forceinline__ unsigned f2tf32(float f) {
    unsigned u;
    asm("cvt.rna.tf32.f32 %0, %1;" : "=r"(u) : "f"(f));
    return u;
}
__device__ __forceinline__ float tf32r(float f) {
    return __uint_as_float(f2tf32(f));
}

// ---------------- fused tf32 rounding: 5 segments in one launch ----------------
__global__ __launch_bounds__(256)
void round_all_kernel(const float* s0, float* d0, size_t n0,
                      const float* s1, float* d1, size_t n1,
                      const float* s2, float* d2, size_t n2,
                      const float* s3, float* d3, size_t n3,
                      const float* s4, float* d4, size_t n4)
{
    size_t i = (size_t)blockIdx.x * blockDim.x + threadIdx.x;
    const float* s; float* d;
    if (i < n0) { s = s0; d = d0; }
    else if ((i -= n0) < n1) { s = s1; d = d1; }
    else if ((i -= n1) < n2) { s = s2; d = d2; }
    else if ((i -= n2) < n3) { s = s3; d = d3; }
    else if ((i -= n3) < n4) { s = s4; d = d4; }
    else return;
    float4 v = ((const float4*)s)[i];
    v.x = tf32r(v.x); v.y = tf32r(v.y); v.z = tf32r(v.z); v.w = tf32r(v.w);
    ((float4*)d)[i] = v;
}

// ---------------- split-K reduce: bc (8 partials) + dtlo (4 partials, tf32r) ----------------
__global__ __launch_bounds__(256)
void reduce_splitk_kernel(const float* __restrict__ bcp, float* __restrict__ bc,
                          const float* __restrict__ dtlp, float* __restrict__ dtlo)
{
    const size_t nBC = (size_t)ML * 32 / 4;
    const size_t nDT = (size_t)ML * DTR / 4;
    size_t i = (size_t)blockIdx.x * blockDim.x + threadIdx.x;
    if (i < nBC) {
        float4 a = ((const float4*)bcp)[i];
        #pragma unroll
        for (int s = 1; s < KS_BC; s++) {
            float4 p = ((const float4*)(bcp + (size_t)s * ML * 32))[i];
            a.x += p.x; a.y += p.y; a.z += p.z; a.w += p.w;
        }
        ((float4*)bc)[i] = a;
    } else if ((i -= nBC) < nDT) {
        float4 a = ((const float4*)dtlp)[i];
        #pragma unroll
        for (int s = 1; s < KS_DT; s++) {
            float4 p = ((const float4*)(dtlp + (size_t)s * ML * DTR))[i];
            a.x += p.x; a.y += p.y; a.z += p.z; a.w += p.w;
        }
        a.x = tf32r(a.x); a.y = tf32r(a.y); a.z = tf32r(a.z); a.w = tf32r(a.w);
        ((float4*)dtlo)[i] = a;
    }
}

// ---------------- async-copy + ldmatrix helpers ----------------
__device__ __forceinline__ void cp16(float* smem_dst, const float* gmem_src) {
    unsigned s = (unsigned)__cvta_generic_to_shared(smem_dst);
    asm volatile("cp.async.cg.shared.global [%0], [%1], 16;\n" :: "r"(s), "l"(gmem_src));
}
__device__ __forceinline__ void cp_commit() {
    asm volatile("cp.async.commit_group;\n");
}
__device__ __forceinline__ void cp_wait1() {
    asm volatile("cp.async.wait_group 1;\n");
}
__device__ __forceinline__ void cp_wait2() {
    asm volatile("cp.async.wait_group 2;\n");
}
__device__ __forceinline__ void ldsm4(unsigned& r0, unsigned& r1, unsigned& r2, unsigned& r3,
                                      unsigned addr) {
    asm volatile("ldmatrix.sync.aligned.m8n8.x4.shared.b16 {%0,%1,%2,%3}, [%4];"
                 : "=r"(r0), "=r"(r1), "=r"(r2), "=r"(r3) : "r"(addr));
}

// =========================================================================
// WIDE TF32 GEMM: BM=128, BN=256, BK=32, 512 threads (16 warps, 2m x 8n),
// warp tile 64x32, 4-stage cp.async (wait_group 2), ldmatrix fragments.
// =========================================================================
#define TSZ_A 4096
#define TSZ_B 8192
#define STB_A 16384u
#define STB_B 32768u

__global__ __launch_bounds__(512, 1)
void mma_gemm_wide(int M, int N, int K,
                   const float* __restrict__ A, int lda,
                   const float* __restrict__ Bw, int ldb,
                   float* __restrict__ C, int ldc)
{
    extern __shared__ float smem[];
    float* As = smem;
    float* Bs = smem + 4*TSZ_A;

    const int tid  = threadIdx.x;
    const int lane = tid & 31;
    const int warp = tid >> 5;
    const int wm   = (warp & 1) * 64;
    const int wn   = (warp >> 1) * 32;
    const int bm   = blockIdx.y * 128;
    const int bn   = blockIdx.x * 256;

    const int q     = tid & 7;
    const int r0    = tid >> 3;
    const int pq    = q ^ (r0 & 7);
    const int dBase = r0*32 + pq*4;

    const float* gA = A  + (size_t)(bm + r0) * lda + q*4;
    const float* gB = Bw + (size_t)(bn + r0) * ldb + q*4;

    const int g    = lane >> 3;
    const int kg   = g >> 1;
    const int sub8 = (g & 1) << 3;
    const int lr   = lane & 7;
    const unsigned aSh = (unsigned)__cvta_generic_to_shared(As);
    const unsigned bSh = (unsigned)__cvta_generic_to_shared(Bs);
    const unsigned aBase  = aSh + (unsigned)(wm + sub8 + lr) * 128;
    const unsigned bBase0 = bSh + (unsigned)(wn + sub8 + lr) * 128;
    const unsigned bBase1 = bBase0 + 16*128;
    unsigned tks[4];
    #pragma unroll
    for (int ks = 0; ks < 4; ks++)
        tks[ks] = (unsigned)(((((ks << 1) + kg) ^ lr) & 7) << 4);

    const int u  = lane >> 2;
    const int li = lane & 3;

    float acc[4][4][4];
    #pragma unroll
    for (int i = 0; i < 4; i++)
        #pragma unroll
        for (int j = 0; j < 4; j++)
            #pragma unroll
            for (int r = 0; r < 4; r++) acc[i][j][r] = 0.0f;

    const int KT = K / 32;

    #pragma unroll
    for (int s = 0; s < 2; s++) {
        const size_t ko = (size_t)s * 32;
        #pragma unroll
        for (int i = 0; i < 2; i++)
            cp16(As + s*TSZ_A + dBase + i*2048, gA + (size_t)i*64*lda + ko);
        #pragma unroll
        for (int i = 0; i < 4; i++)
            cp16(Bs + s*TSZ_B + dBase + i*2048, gB + (size_t)i*64*ldb + ko);
        cp_commit();
    }

    for (int kt = 0; kt < KT; kt++) {
        const int cur = kt & 3;
        if (kt + 2 < KT) {
            const int st = (kt + 2) & 3;
            const size_t ko = (size_t)(kt + 2) * 32;
            #pragma unroll
            for (int i = 0; i < 2; i++)
                cp16(As + st*TSZ_A + dBase + i*2048, gA + (size_t)i*64*lda + ko);
            #pragma unroll
            for (int i = 0; i < 4; i++)
                cp16(Bs + st*TSZ_B + dBase + i*2048, gB + (size_t)i*64*ldb + ko);
        }
        cp_commit();
        cp_wait2();
        __syncthreads();

        const unsigned aOff  = aBase  + (unsigned)cur * STB_A;
        const unsigned bOff0 = bBase0 + (unsigned)cur * STB_B;
        const unsigned bOff1 = bBase1 + (unsigned)cur * STB_B;

        #pragma unroll
        for (int ks = 0; ks < 4; ks++) {
            unsigned af[4][4];
            unsigned bf[4][2];
            #pragma unroll
            for (int i = 0; i < 4; i++)
                ldsm4(af[i][0], af[i][1], af[i][2], af[i][3],
                      aOff + (unsigned)i*2048 + tks[ks]);
            ldsm4(bf[0][0], bf[1][0], bf[0][1], bf[1][1], bOff0 + tks[ks]);
            ldsm4(bf[2][0], bf[3][0], bf[2][1], bf[3][1], bOff1 + tks[ks]);

            #pragma unroll
            for (int i = 0; i < 4; i++)
                #pragma unroll
                for (int j = 0; j < 4; j++) {
                    asm volatile(
                        "mma.sync.aligned.m16n8k8.row.col.f32.tf32.tf32.f32 "
                        "{%0,%1,%2,%3}, {%4,%5,%6,%7}, {%8,%9}, {%0,%1,%2,%3};"
                        : "+f"(acc[i][j][0]), "+f"(acc[i][j][1]),
                          "+f"(acc[i][j][2]), "+f"(acc[i][j][3])
                        : "r"(af[i][0]), "r"(af[i][1]), "r"(af[i][2]), "r"(af[i][3]),
                          "r"(bf[j][0]), "r"(bf[j][1]));
                }
        }
    }

    #pragma unroll
    for (int i = 0; i < 4; i++) {
        const int r0e = bm + wm + i*16 + u;
        #pragma unroll
        for (int j = 0; j < 4; j++) {
            const int c0 = bn + wn + j*8 + li*2;
            *(float2*)&C[(size_t)r0e * ldc + c0]     = make_float2(acc[i][j][0], acc[i][j][1]);
            *(float2*)&C[(size_t)(r0e+8) * ldc + c0] = make_float2(acc[i][j][2], acc[i][j][3]);
        }
    }
}

// ================= mma.sync TF32 GEMM BN=128 =================
// EPI: 0 = none, 1 = softplus(v+bias[n])
// SPLITK: blockIdx.x = k-split index (N must be 128); partial -> C + split*M*ldc
#define TSZ32 4096
#define STB   16384u

template<int EPI, int SPLITK>
__global__ __launch_bounds__(256, 2)
void mma_gemm(int M, int N, int K,
              const float* __restrict__ A, int lda,
              const float* __restrict__ Bw, int ldb,
              float* __restrict__ C, int ldc,
              const float* __restrict__ bias)
{
    extern __shared__ float smem[];
    float* As = smem;
    float* Bs = smem + 3*TSZ32;

    const int tid  = threadIdx.x;
    const int lane = tid & 31;
    const int warp = tid >> 5;
    const int wm   = (warp & 1) * 64;
    const int wn   = (warp >> 1) * 32;
    const int bm   = blockIdx.y * 128;
    int bn = 0;
    if (SPLITK) {
        const int sk = blockIdx.x;
        A  += (size_t)sk * K;
        Bw += (size_t)sk * K;
        C  += (size_t)sk * M * ldc;
    } else {
        bn = blockIdx.x * 128;
    }

    const int q     = tid & 7;
    const int r0    = tid >> 3;
    const int pq    = q ^ (r0 & 7);
    const int dBase = r0*32 + pq*4;

    const float* gA = A  + (size_t)(bm + r0) * lda + q*4;
    const float* gB = Bw + (size_t)(bn + r0) * ldb + q*4;

    const int g    = lane >> 3;
    const int kg   = g >> 1;
    const int sub8 = (g & 1) << 3;
    const int lr   = lane & 7;
    const unsigned aSh = (unsigned)__cvta_generic_to_shared(As);
    const unsigned bSh = (unsigned)__cvta_generic_to_shared(Bs);
    const unsigned aBase  = aSh + (unsigned)(wm + sub8 + lr) * 128;
    const unsigned bBase0 = bSh + (unsigned)(wn + sub8 + lr) * 128;
    const unsigned bBase1 = bBase0 + 16*128;
    unsigned tks[4];
    #pragma unroll
    for (int ks = 0; ks < 4; ks++)
        tks[ks] = (unsigned)(((((ks << 1) + kg) ^ lr) & 7) << 4);

    const int u  = lane >> 2;
    const int li = lane & 3;

    float acc[4][4][4];
    #pragma unroll
    for (int i = 0; i < 4; i++)
        #pragma unroll
        for (int j = 0; j < 4; j++)
            #pragma unroll
            for (int r = 0; r < 4; r++) acc[i][j][r] = 0.0f;

    const int KT = K / 32;

    #pragma unroll
    for (int s = 0; s < 2; s++) {
        const size_t ko = (size_t)s * 32;
        #pragma unroll
        for (int i = 0; i < 4; i++) {
            cp16(As + s*TSZ32 + dBase + i*1024, gA + (size_t)i*32*lda + ko);
            cp16(Bs + s*TSZ32 + dBase + i*1024, gB + (size_t)i*32*ldb + ko);
        }
        cp_commit();
    }
    cp_wait1();
    __syncthreads();

    for (int kt = 0; kt < KT; kt++) {
        const int cur = kt % 3;
        if (kt + 2 < KT) {
            const int st = (kt + 2) % 3;
            const size_t ko = (size_t)(kt + 2) * 32;
            #pragma unroll
            for (int i = 0; i < 4; i++) {
                cp16(As + st*TSZ32 + dBase + i*1024, gA + (size_t)i*32*lda + ko);
                cp16(Bs + st*TSZ32 + dBase + i*1024, gB + (size_t)i*32*ldb + ko);
            }
        }
        cp_commit();

        const unsigned aOff  = aBase  + (unsigned)cur * STB;
        const unsigned bOff0 = bBase0 + (unsigned)cur * STB;
        const unsigned bOff1 = bBase1 + (unsigned)cur * STB;

        #pragma unroll
        for (int ks = 0; ks < 4; ks++) {
            unsigned af[4][4];
            unsigned bf[4][2];
            #pragma unroll
            for (int i = 0; i < 4; i++)
                ldsm4(af[i][0], af[i][1], af[i][2], af[i][3],
                      aOff + (unsigned)i*2048 + tks[ks]);
            ldsm4(bf[0][0], bf[1][0], bf[0][1], bf[1][1], bOff0 + tks[ks]);
            ldsm4(bf[2][0], bf[3][0], bf[2][1], bf[3][1], bOff1 + tks[ks]);

            #pragma unroll
            for (int i = 0; i < 4; i++)
                #pragma unroll
                for (int j = 0; j < 4; j++) {
                    asm volatile(
                        "mma.sync.aligned.m16n8k8.row.col.f32.tf32.tf32.f32 "
                        "{%0,%1,%2,%3}, {%4,%5,%6,%7}, {%8,%9}, {%0,%1,%2,%3};"
                        : "+f"(acc[i][j][0]), "+f"(acc[i][j][1]),
                          "+f"(acc[i][j][2]), "+f"(acc[i][j][3])
                        : "r"(af[i][0]), "r"(af[i][1]), "r"(af[i][2]), "r"(af[i][3]),
                          "r"(bf[j][0]), "r"(bf[j][1]));
                }
        }

        cp_wait1();
        __syncthreads();
    }

    #pragma unroll
    for (int i = 0; i < 4; i++) {
        const int r0e = bm + wm + i*16 + u;
        #pragma unroll
        for (int j = 0; j < 4; j++) {
            const int c0 = bn + wn + j*8 + li*2;
            float v0 = acc[i][j][0], v1 = acc[i][j][1];
            float v2 = acc[i][j][2], v3 = acc[i][j][3];
            if (EPI == 1) {
                const float bA = bias[c0], bB = bias[c0+1];
                v0 += bA; v1 += bB; v2 += bA; v3 += bB;
                v0 = (v0 > 20.0f) ? v0 : log1pf(__expf(v0));
                v1 = (v1 > 20.0f) ? v1 : log1pf(__expf(v1));
                v2 = (v2 > 20.0f) ? v2 : log1pf(__expf(v2));
                v3 = (v3 > 20.0f) ? v3 : log1pf(__expf(v3));
            }
            *(float2*)&C[(size_t)r0e * ldc + c0]     = make_float2(v0, v1);
            *(float2*)&C[(size_t)(r0e+8) * ldc + c0] = make_float2(v2, v3);
        }
    }
}

// ---------------- fp32 tiled SGEMM, split-K (B/C part of x_proj: N=32) ----------------
template<int BM, int BN, int BK, int TM, int TN>
__global__ __launch_bounds__(256)
void sgemm_splitk_kernel(int M, int N, int KC,
                         const float* __restrict__ A, int lda,
                         const float* __restrict__ Bw, int ldb,
                         float* __restrict__ C, int ldc)
{
    __shared__ float As[BK][BM];
    __shared__ float Bs[BK][BN];

    const int tid = threadIdx.x;
    const int tx  = tid & 15;
    const int ty  = tid >> 4;
    const int bm  = blockIdx.y * BM;
    const int sk  = blockIdx.x;
    const size_t k0base = (size_t)sk * KC;
    C += (size_t)sk * M * ldc;

    float acc[TM][TN];
    #pragma unroll
    for (int i = 0; i < TM; i++)
        #pragma unroll
        for (int j = 0; j < TN; j++) acc[i][j] = 0.0f;

    const int a_m = tid / (BK/4);
    const int a_k = (tid % (BK/4)) * 4;

    for (int k0 = 0; k0 < KC; k0 += BK) {
        if (tid < (BM*BK/4)) {
            float4 v = *(const float4*)&A[(size_t)(bm + a_m)*lda + k0base + k0 + a_k];
            As[a_k+0][a_m] = v.x; As[a_k+1][a_m] = v.y;
            As[a_k+2][a_m] = v.z; As[a_k+3][a_m] = v.w;
        }
        if (tid < (BN*BK/4)) {
            float4 v = *(const float4*)&Bw[(size_t)a_m*ldb + k0base + k0 + a_k];
            Bs[a_k+0][a_m] = v.x; Bs[a_k+1][a_m] = v.y;
            Bs[a_k+2][a_m] = v.z; Bs[a_k+3][a_m] = v.w;
        }
        __syncthreads();

        #pragma unroll
        for (int k = 0; k < BK; k++) {
            float rm[TM], rn[TN];
            #pragma unroll
            for (int i = 0; i < TM; i++) rm[i] = As[k][ty*TM + i];
            #pragma unroll
            for (int j = 0; j < TN; j++) rn[j] = Bs[k][tx*TN + j];
            #pragma unroll
            for (int i = 0; i < TM; i++)
                #pragma unroll
                for (int j = 0; j < TN; j++)
                    acc[i][j] += rm[i] * rn[j];
        }
        __syncthreads();
    }

    #pragma unroll
    for (int i = 0; i < TM; i++) {
        const int m = bm + ty*TM + i;
        #pragma unroll
        for (int j = 0; j < TN; j++) {
            const int n = tx*TN + j;
            C[(size_t)m*ldc + n] = acc[i][j];
        }
    }
}

// ---------------- depthwise causal conv(k=4) + bias + silu, L-chunked ----------------
#define CLC 128
__global__ __launch_bounds__(256)
void conv_silu_kernel(const float* __restrict__ xz,
                      const float* __restrict__ w,
                      const float* __restrict__ bias,
                      float* __restrict__ xc,
                      float* __restrict__ xcr)
{
    const int d  = blockIdx.x * blockDim.x + threadIdx.x;
    const int b  = blockIdx.z;
    const int l0 = blockIdx.y * CLC;

    const float w0 = w[d*4+0], w1 = w[d*4+1], w2 = w[d*4+2], w3 = w[d*4+3];
    const float bi = bias[d];
    const float* px = xz  + ((size_t)b * L_ + l0) * EI + d;
    float*       po = xc  + ((size_t)b * L_ + l0) * DI + d;
    float*       pr = xcr + ((size_t)b * L_ + l0) * DI + d;

    float x0 = 0.f, x1 = 0.f, x2 = 0.f;
    if (l0 > 0) {
        x0 = px[-(size_t)3 * EI];
        x1 = px[-(size_t)2 * EI];
        x2 = px[-(size_t)1 * EI];
    }
    #pragma unroll 4
    for (int l = 0; l < CLC; l++) {
        float x3 = px[(size_t)l * EI];
        float v  = w0*x0 + w1*x1 + w2*x2 + w3*x3 + bi;
        v = v / (1.0f + __expf(-v));
        po[(size_t)l * DI] = v;
        pr[(size_t)l * DI] = tf32r(v);
        x0 = x1; x1 = x2; x2 = x3;
    }
}

// ---------------- selective scan: state-parallel + cp.async smem staging ----------------
// 128 threads = 32 channels x 4 state-lanes. Chunks of SCH=16 timesteps double-
// buffered in smem; prefetch distance = 1 chunk (~640 compute cycles > DRAM lat).
#define SCH 16
__global__ __launch_bounds__(128)
void scan_kernel(const float* __restrict__ xz,
                 const float* __restrict__ xc,
                 const float* __restrict__ dt,
                 const float* __restrict__ bc,
                 const float* __restrict__ A_log,
                 const float* __restrict__ Dp,
                 float* __restrict__ y)
{
    __shared__ float s_dt[2][SCH][32];
    __shared__ float s_xc[2][SCH][32];
    __shared__ float s_z [2][SCH][32];
    __shared__ float s_bc[2][SCH][32];

    const int b    = blockIdx.y;
    const int tid  = threadIdx.x;
    const int wid  = tid >> 5;
    const int lane = tid & 31;
    const int sub  = lane & 3;                       // state group 0..3
    const int cidx = wid * 8 + (lane >> 2);          // channel within block 0..31
    const int d0   = blockIdx.x * 32;
    const int d    = d0 + cidx;

    // loader mapping: 1 cp16 per array per chunk
    const int lrow = tid >> 3;                       // 0..15
    const int lcol = (tid & 7) * 4;                  // 0,4,..28

    float negA[4];
    #pragma unroll
    for (int j = 0; j < 4; j++)
        negA[j] = -__expf(A_log[d*DS + sub*4 + j]);
    const float negA0 = -__expf(A_log[d*DS]);

    bool chain = (negA0 != 0.0f);
    #pragma unroll
    for (int n = 1; n < DS; n++) {
        float na = -__expf(A_log[d*DS + n]);
        float r  = na - (float)(n+1) * negA0;
        if (fabsf(r) > 1e-4f * fabsf(na)) chain = false;
    }

    const float Dd = Dp[d];
    float h[4] = {0.f, 0.f, 0.f, 0.f};

    const size_t rb = (size_t)b * L_;
    const float* pdt = dt + rb * DI;
    const float* pxc = xc + rb * DI;
    const float* pz  = xz + rb * EI + DI;
    const float* pbc = bc + rb * 32;
    float*       py  = y  + rb * DI + d;

    // issue chunk 0 and 1
    #pragma unroll
    for (int c = 0; c < 2; c++) {
        const size_t l0 = (size_t)c * SCH;
        cp16(&s_dt[c][lrow][lcol], pdt + (l0 + lrow) * DI + d0 + lcol);
        cp16(&s_xc[c][lrow][lcol], pxc + (l0 + lrow) * DI + d0 + lcol);
        cp16(&s_z [c][lrow][lcol], pz  + (l0 + lrow) * EI + d0 + lcol);
        cp16(&s_bc[c][lrow][lcol], pbc + (l0 + lrow) * 32 + lcol);
        cp_commit();
    }
    cp_wait1();
    __syncthreads();

    const int NCH = L_ / SCH;
    for (int c = 0; c < NCH; c++) {
        const int buf = c & 1;

        #pragma unroll 4
        for (int i = 0; i < SCH; i++) {
            const float dtv = s_dt[buf][i][cidx];
            const float xv  = s_xc[buf][i][cidx];
            const float zv  = s_z [buf][i][cidx];
            const float bc0 = s_bc[buf][i][lane];

            float dA[4];
            if (chain) {
                const float b1 = __expf(dtv * negA0);
                const float b2 = b1*b1, b3 = b2*b1, b4 = b2*b2;
                const float b8 = b4*b4, b12 = b8*b4;
                const float pw = (sub == 0) ? 1.0f : (sub == 1) ? b4 : (sub == 2) ? b8 : b12;
                dA[0] = pw*b1; dA[1] = pw*b2; dA[2] = pw*b3; dA[3] = pw*b4;
            } else {
                #pragma unroll
                for (int j = 0; j < 4; j++) dA[j] = __expf(dtv * negA[j]);
            }

            const float du = dtv * xv;
            float yp = 0.0f;
            #pragma unroll
            for (int j = 0; j < 4; j++) {
                const float Bn = __shfl_sync(0xFFFFFFFFu, bc0, sub*4 + j);
                const float Cn = __shfl_sync(0xFFFFFFFFu, bc0, 16 + sub*4 + j);
                h[j] = h[j] * dA[j] + du * Bn;
                yp  += h[j] * Cn;
            }
            yp += __shfl_xor_sync(0xFFFFFFFFu, yp, 1);
            yp += __shfl_xor_sync(0xFFFFFFFFu, yp, 2);

            if (sub == 0) {
                const float yv = yp + xv * Dd;
                const float zs = zv / (1.0f + __expf(-zv));
                py[(size_t)(c*SCH + i) * DI] = tf32r(yv * zs);
            }
        }

        __syncthreads();   // all threads done reading buf
        if (c + 2 < NCH) {
            const size_t l0 = (size_t)(c + 2) * SCH;
            cp16(&s_dt[buf][lrow][lcol], pdt + (l0 + lrow) * DI + d0 + lcol);
            cp16(&s_xc[buf][lrow][lcol], pxc + (l0 + lrow) * DI + d0 + lcol);
            cp16(&s_z [buf][lrow][lcol], pz  + (l0 + lrow) * EI + d0 + lcol);
            cp16(&s_bc[buf][lrow][lcol], pbc + (l0 + lrow) * 32 + lcol);
        }
        cp_commit();
        cp_wait1();        // chunk c+1 resident
        __syncthreads();
    }
}

// ---------------- launch ----------------
extern "C" void kernel_launch(void* const* d_in, const int* in_sizes, int n_in,
                              void* d_out, int out_size)
{
    const float* hs    = (const float*)d_in[0];
    const float* w_in  = (const float*)d_in[1];
    const float* convw = (const float*)d_in[2];
    const float* convb = (const float*)d_in[3];
    const float* xpw   = (const float*)d_in[4];
    const float* dtw   = (const float*)d_in[5];
    const float* dtb   = (const float*)d_in[6];
    const float* outw  = (const float*)d_in[7];
    const float* Alog  = (const float*)d_in[8];
    const float* Dp    = (const float*)d_in[9];
    float*       out   = (float*)d_out;

    float *xz, *xc, *xcr, *bc, *bcp, *dtb_, *yb;
    float *hsc, *winc, *dtwc, *outwc, *xpwc, *dtlo, *dtlp;
    cudaGetSymbolAddress((void**)&xz,    g_xz);
    cudaGetSymbolAddress((void**)&xc,    g_xc);
    cudaGetSymbolAddress((void**)&xcr,   g_xcr);
    cudaGetSymbolAddress((void**)&bc,    g_bc);
    cudaGetSymbolAddress((void**)&bcp,   g_bcp);
    cudaGetSymbolAddress((void**)&dtb_,  g_dt);
    cudaGetSymbolAddress((void**)&yb,    g_y);
    cudaGetSymbolAddress((void**)&hsc,   g_hsc);
    cudaGetSymbolAddress((void**)&winc,  g_winc);
    cudaGetSymbolAddress((void**)&dtwc,  g_dtwc);
    cudaGetSymbolAddress((void**)&outwc, g_outwc);
    cudaGetSymbolAddress((void**)&xpwc,  g_xpwc);
    cudaGetSymbolAddress((void**)&dtlo,  g_dtlo);
    cudaGetSymbolAddress((void**)&dtlp,  g_dtlp);

    const dim3 t256(256);
    const size_t msmem = 6 * TSZ32 * sizeof(float);
    const size_t wsmem = 4 * (TSZ_A + TSZ_B) * sizeof(float);

    cudaFuncSetAttribute((const void*)&mma_gemm<1,0>, cudaFuncAttributeMaxDynamicSharedMemorySize, (int)msmem);
    cudaFuncSetAttribute((const void*)&mma_gemm<0,1>, cudaFuncAttributeMaxDynamicSharedMemorySize, (int)msmem);
    cudaFuncSetAttribute((const void*)&mma_gemm_wide, cudaFuncAttributeMaxDynamicSharedMemorySize, (int)wsmem);

    // 0) fused tf32 pre-rounding
    {
        const size_t n0 = (size_t)ML*DM/4, n1 = (size_t)EI*DM/4,
                     n2 = (size_t)DI*DTR/4, n3 = (size_t)DM*DI/4,
                     n4 = (size_t)DTR*DI/4;
        const size_t nt = n0 + n1 + n2 + n3 + n4;
        round_all_kernel<<<(unsigned)((nt+255)/256), t256>>>(
            hs, hsc, n0, w_in, winc, n1, dtw, dtwc, n2, outw, outwc, n3, xpw, xpwc, n4);
    }

    // 1) in_proj (wide tf32 mma)
    mma_gemm_wide<<<dim3(EI/256, ML/128), dim3(512), wsmem>>>(
        ML, EI, DM, hsc, DM, winc, DM, xz, EI);

    // 2) depthwise conv + silu
    conv_silu_kernel<<<dim3(DI/256, L_/CLC, B_), t256>>>(xz, convw, convb, xc, xcr);

    // 3a) x_proj B/C (fp32 split-K x8)
    sgemm_splitk_kernel<64,32,16,4,2><<<dim3(KS_BC, ML/64), t256>>>(
        ML, 32, DI/KS_BC, xc, DI, xpw + (size_t)DTR*DI, DI, bcp, 32);

    // 3b) x_proj dt_lo (tf32 mma split-K x4)
    mma_gemm<0,1><<<dim3(KS_DT, ML/128), t256, msmem>>>(
        ML, DTR, DI/KS_DT, xcr, DI, xpwc, DI, dtlp, DTR, nullptr);

    // 3c) reduce split-K partials
    {
        const size_t nt = (size_t)ML*32/4 + (size_t)ML*DTR/4;
        reduce_splitk_kernel<<<(unsigned)((nt+255)/256), t256>>>(bcp, bc, dtlp, dtlo);
    }

    // 4) dt_proj + softplus (tf32 mma)
    mma_gemm<1,0><<<dim3(DI/128, ML/128), t256, msmem>>>(
        ML, DI, DTR, dtlo, DTR, dtwc, DTR, dtb_, DI, dtb);

    // 5) selective scan (state-parallel, cp.async staged)
    scan_kernel<<<dim3(DI/32, B_), dim3(128)>>>(
        xz, xc, dtb_, bc, Alog, Dp, yb);

    // 6) out_proj (wide tf32 mma)
    mma_gemm_wide<<<dim3(DM/256, ML/128), dim3(512), wsmem>>>(
        ML, DM, DI, yb, DI, outwc, DI, out, DM);
}